// round 2
// baseline (speedup 1.0000x reference)
#include <cuda_runtime.h>
#include <math.h>

#define D      256
#define D4     64          // D / 4 (float4 units per row)
#define NMAX   50000
#define TILE   64
#define KT     16
#define BN_EPS 1e-5f

// Scratch (allocation-free contract): agg buffer + mid activation buffer
__device__ float g_agg[(size_t)NMAX * D];
__device__ float g_mid[(size_t)NMAX * D];

// ---------------------------------------------------------------------------
// Kernel 1: zero the aggregation buffer (must happen every launch)
// ---------------------------------------------------------------------------
__global__ void zero_agg_kernel(int n4) {
    int i = blockIdx.x * blockDim.x + threadIdx.x;
    if (i < n4) {
        float4 z = make_float4(0.f, 0.f, 0.f, 0.f);
        reinterpret_cast<float4*>(g_agg)[i] = z;
    }
}

// ---------------------------------------------------------------------------
// Kernel 2: scatter  agg[dst] += relu(x[src] + edge_attr)
// One thread per (edge, float4-chunk). 64 chunks per edge.
// edge_index is int32 (JAX x64 disabled -> int64 request materializes int32).
// ---------------------------------------------------------------------------
__global__ void scatter_kernel(const float* __restrict__ x,
                               const int* __restrict__ ei,
                               const float* __restrict__ ea,
                               int E) {
    long long i = (long long)blockIdx.x * blockDim.x + threadIdx.x;
    int e = (int)(i >> 6);
    int c = (int)(i & 63);
    if (e >= E) return;

    int s = ei[e];
    int d = ei[E + e];

    float4 xv = reinterpret_cast<const float4*>(x)[(size_t)s * D4 + c];
    float4 av = reinterpret_cast<const float4*>(ea)[(size_t)e * D4 + c];
    float4 m;
    m.x = fmaxf(xv.x + av.x, 0.f);
    m.y = fmaxf(xv.y + av.y, 0.f);
    m.z = fmaxf(xv.z + av.z, 0.f);
    m.w = fmaxf(xv.w + av.w, 0.f);

    // sm_90+ vector atomic: one 16B L2 reduction instead of 4 scalar ones
    atomicAdd(&reinterpret_cast<float4*>(g_agg)[(size_t)d * D4 + c], m);
}

// ---------------------------------------------------------------------------
// GEMM 1:  g_mid = gelu( bn1(2x + agg) @ W1^T + b1 )
//   A[n,k] = bn1(2*x[n,k] + agg[n,k])   (computed on load)
//   B[j,k] = W1[j,k]                     (NT gemm, both K-contiguous)
// 64x64 block tile, KT=16 k-tile, 256 threads, 4x4 per thread.
// ---------------------------------------------------------------------------
__global__ void gemm1_kernel(const float* __restrict__ x,
                             const float* __restrict__ W1,
                             const float* __restrict__ b1,
                             const float* __restrict__ g1,
                             const float* __restrict__ be1,
                             const float* __restrict__ mu1,
                             const float* __restrict__ va1,
                             int N) {
    __shared__ float As[KT][TILE];
    __shared__ float Bs[KT][TILE];
    __shared__ float sS[D];   // bn1 scale per k
    __shared__ float sT[D];   // bn1 shift per k

    const int tid = threadIdx.x;
    const int tx  = tid & 15;          // 0..15 -> output cols
    const int ty  = tid >> 4;          // 0..15 -> output rows
    const int m0  = blockIdx.y * TILE;
    const int j0  = blockIdx.x * TILE;

    // Precompute bn1 affine: s = gamma*rsqrt(var+eps), t = beta - mean*s
    if (tid < D) {
        float sc = g1[tid] * rsqrtf(va1[tid] + BN_EPS);
        sS[tid] = sc;
        sT[tid] = be1[tid] - mu1[tid] * sc;
    }
    __syncthreads();

    float acc[4][4];
#pragma unroll
    for (int i = 0; i < 4; i++)
#pragma unroll
        for (int j = 0; j < 4; j++) acc[i][j] = 0.f;

    const int lrow = tid >> 2;         // 0..63
    const int lk4  = tid & 3;          // 0..3 -> which float4 along k-tile

    for (int kk = 0; kk < D; kk += KT) {
        // ---- load A tile: bn1(2x+agg), transposed into As[k][row]
        {
            int row = m0 + lrow;
            float4 h;
            if (row < N) {
                float4 xv = reinterpret_cast<const float4*>(x)[(size_t)row * D4 + (kk >> 2) + lk4];
                float4 ag = reinterpret_cast<const float4*>(g_agg)[(size_t)row * D4 + (kk >> 2) + lk4];
                h.x = 2.f * xv.x + ag.x;
                h.y = 2.f * xv.y + ag.y;
                h.z = 2.f * xv.z + ag.z;
                h.w = 2.f * xv.w + ag.w;
            } else {
                h = make_float4(0.f, 0.f, 0.f, 0.f);
            }
            int kb = kk + lk4 * 4;
            As[lk4 * 4 + 0][lrow] = h.x * sS[kb + 0] + sT[kb + 0];
            As[lk4 * 4 + 1][lrow] = h.y * sS[kb + 1] + sT[kb + 1];
            As[lk4 * 4 + 2][lrow] = h.z * sS[kb + 2] + sT[kb + 2];
            As[lk4 * 4 + 3][lrow] = h.w * sS[kb + 3] + sT[kb + 3];
        }
        // ---- load B tile: W1 rows j0..j0+63
        {
            int j = j0 + lrow;
            float4 w = reinterpret_cast<const float4*>(W1)[(size_t)j * D4 + (kk >> 2) + lk4];
            Bs[lk4 * 4 + 0][lrow] = w.x;
            Bs[lk4 * 4 + 1][lrow] = w.y;
            Bs[lk4 * 4 + 2][lrow] = w.z;
            Bs[lk4 * 4 + 3][lrow] = w.w;
        }
        __syncthreads();

#pragma unroll
        for (int k = 0; k < KT; k++) {
            float4 a = *reinterpret_cast<const float4*>(&As[k][ty * 4]);
            float4 b = *reinterpret_cast<const float4*>(&Bs[k][tx * 4]);
            acc[0][0] += a.x * b.x; acc[0][1] += a.x * b.y; acc[0][2] += a.x * b.z; acc[0][3] += a.x * b.w;
            acc[1][0] += a.y * b.x; acc[1][1] += a.y * b.y; acc[1][2] += a.y * b.z; acc[1][3] += a.y * b.w;
            acc[2][0] += a.z * b.x; acc[2][1] += a.z * b.y; acc[2][2] += a.z * b.z; acc[2][3] += a.z * b.w;
            acc[3][0] += a.w * b.x; acc[3][1] += a.w * b.y; acc[3][2] += a.w * b.z; acc[3][3] += a.w * b.w;
        }
        __syncthreads();
    }

    // Epilogue: + b1, exact GELU, store to g_mid
    float4 bb = reinterpret_cast<const float4*>(b1)[(j0 >> 2) + tx];
    float bv[4] = {bb.x, bb.y, bb.z, bb.w};
#pragma unroll
    for (int i = 0; i < 4; i++) {
        int row = m0 + ty * 4 + i;
        if (row >= N) continue;
        float4 o;
        float u;
        u = acc[i][0] + bv[0]; o.x = 0.5f * u * (1.f + erff(u * 0.70710678118f));
        u = acc[i][1] + bv[1]; o.y = 0.5f * u * (1.f + erff(u * 0.70710678118f));
        u = acc[i][2] + bv[2]; o.z = 0.5f * u * (1.f + erff(u * 0.70710678118f));
        u = acc[i][3] + bv[3]; o.w = 0.5f * u * (1.f + erff(u * 0.70710678118f));
        reinterpret_cast<float4*>(g_mid)[(size_t)row * D4 + (j0 >> 2) + tx] = o;
    }
}

// ---------------------------------------------------------------------------
// GEMM 2:  out = bn2( (2x+agg) + g_mid @ W2^T + b2 )
// ---------------------------------------------------------------------------
__global__ void gemm2_kernel(const float* __restrict__ x,
                             const float* __restrict__ W2,
                             const float* __restrict__ b2,
                             const float* __restrict__ g2,
                             const float* __restrict__ be2,
                             const float* __restrict__ mu2,
                             const float* __restrict__ va2,
                             float* __restrict__ out,
                             int N) {
    __shared__ float As[KT][TILE];
    __shared__ float Bs[KT][TILE];

    const int tid = threadIdx.x;
    const int tx  = tid & 15;
    const int ty  = tid >> 4;
    const int m0  = blockIdx.y * TILE;
    const int j0  = blockIdx.x * TILE;

    float acc[4][4];
#pragma unroll
    for (int i = 0; i < 4; i++)
#pragma unroll
        for (int j = 0; j < 4; j++) acc[i][j] = 0.f;

    const int lrow = tid >> 2;
    const int lk4  = tid & 3;

    for (int kk = 0; kk < D; kk += KT) {
        {
            int row = m0 + lrow;
            float4 h = make_float4(0.f, 0.f, 0.f, 0.f);
            if (row < N)
                h = reinterpret_cast<const float4*>(g_mid)[(size_t)row * D4 + (kk >> 2) + lk4];
            As[lk4 * 4 + 0][lrow] = h.x;
            As[lk4 * 4 + 1][lrow] = h.y;
            As[lk4 * 4 + 2][lrow] = h.z;
            As[lk4 * 4 + 3][lrow] = h.w;
        }
        {
            int j = j0 + lrow;
            float4 w = reinterpret_cast<const float4*>(W2)[(size_t)j * D4 + (kk >> 2) + lk4];
            Bs[lk4 * 4 + 0][lrow] = w.x;
            Bs[lk4 * 4 + 1][lrow] = w.y;
            Bs[lk4 * 4 + 2][lrow] = w.z;
            Bs[lk4 * 4 + 3][lrow] = w.w;
        }
        __syncthreads();

#pragma unroll
        for (int k = 0; k < KT; k++) {
            float4 a = *reinterpret_cast<const float4*>(&As[k][ty * 4]);
            float4 b = *reinterpret_cast<const float4*>(&Bs[k][tx * 4]);
            acc[0][0] += a.x * b.x; acc[0][1] += a.x * b.y; acc[0][2] += a.x * b.z; acc[0][3] += a.x * b.w;
            acc[1][0] += a.y * b.x; acc[1][1] += a.y * b.y; acc[1][2] += a.y * b.z; acc[1][3] += a.y * b.w;
            acc[2][0] += a.z * b.x; acc[2][1] += a.z * b.y; acc[2][2] += a.z * b.z; acc[2][3] += a.z * b.w;
            acc[3][0] += a.w * b.x; acc[3][1] += a.w * b.y; acc[3][2] += a.w * b.z; acc[3][3] += a.w * b.w;
        }
        __syncthreads();
    }

    // Epilogue: f = acc + b2 ; h = 2x+agg ; out = (h+f)*s2 + t2
    int c4 = (j0 >> 2) + tx;
    float4 bb = reinterpret_cast<const float4*>(b2)[c4];
    float4 ga = reinterpret_cast<const float4*>(g2)[c4];
    float4 be = reinterpret_cast<const float4*>(be2)[c4];
    float4 mu = reinterpret_cast<const float4*>(mu2)[c4];
    float4 va = reinterpret_cast<const float4*>(va2)[c4];
    float s2[4], t2[4];
    s2[0] = ga.x * rsqrtf(va.x + BN_EPS); t2[0] = be.x - mu.x * s2[0];
    s2[1] = ga.y * rsqrtf(va.y + BN_EPS); t2[1] = be.y - mu.y * s2[1];
    s2[2] = ga.z * rsqrtf(va.z + BN_EPS); t2[2] = be.z - mu.z * s2[2];
    s2[3] = ga.w * rsqrtf(va.w + BN_EPS); t2[3] = be.w - mu.w * s2[3];
    float bv[4] = {bb.x, bb.y, bb.z, bb.w};

#pragma unroll
    for (int i = 0; i < 4; i++) {
        int row = m0 + ty * 4 + i;
        if (row >= N) continue;
        float4 xv = reinterpret_cast<const float4*>(x)[(size_t)row * D4 + c4];
        float4 ag = reinterpret_cast<const float4*>(g_agg)[(size_t)row * D4 + c4];
        float4 o;
        float h, f;
        h = 2.f * xv.x + ag.x; f = acc[i][0] + bv[0]; o.x = (h + f) * s2[0] + t2[0];
        h = 2.f * xv.y + ag.y; f = acc[i][1] + bv[1]; o.y = (h + f) * s2[1] + t2[1];
        h = 2.f * xv.z + ag.z; f = acc[i][2] + bv[2]; o.z = (h + f) * s2[2] + t2[2];
        h = 2.f * xv.w + ag.w; f = acc[i][3] + bv[3]; o.w = (h + f) * s2[3] + t2[3];
        reinterpret_cast<float4*>(out)[(size_t)row * D4 + c4] = o;
    }
}

// ---------------------------------------------------------------------------
extern "C" void kernel_launch(void* const* d_in, const int* in_sizes, int n_in,
                              void* d_out, int out_size) {
    const float* x   = (const float*)d_in[0];
    const int*   ei  = (const int*)d_in[1];     // int32 (JAX default x64 off)
    const float* ea  = (const float*)d_in[2];
    const float* W1  = (const float*)d_in[3];
    const float* b1  = (const float*)d_in[4];
    const float* W2  = (const float*)d_in[5];
    const float* b2  = (const float*)d_in[6];
    const float* g1  = (const float*)d_in[7];
    const float* be1 = (const float*)d_in[8];
    const float* mu1 = (const float*)d_in[9];
    const float* va1 = (const float*)d_in[10];
    const float* g2  = (const float*)d_in[11];
    const float* be2 = (const float*)d_in[12];
    const float* mu2 = (const float*)d_in[13];
    const float* va2 = (const float*)d_in[14];
    float*       out = (float*)d_out;

    int N = in_sizes[0] / D;
    int E = in_sizes[2] / D;

    // 1) zero agg
    int n4 = N * D4;
    zero_agg_kernel<<<(n4 + 255) / 256, 256>>>(n4);

    // 2) scatter relu(x[src]+ea) into agg[dst]
    long long total = (long long)E * 64;
    int sblocks = (int)((total + 255) / 256);
    scatter_kernel<<<sblocks, 256>>>(x, ei, ea, E);

    // 3) GEMM1: g_mid = gelu(bn1(2x+agg) @ W1^T + b1)
    dim3 grid(D / TILE, (N + TILE - 1) / TILE);
    gemm1_kernel<<<grid, 256>>>(x, W1, b1, g1, be1, mu1, va1, N);

    // 4) GEMM2: out = bn2(2x+agg + g_mid @ W2^T + b2)
    gemm2_kernel<<<grid, 256>>>(x, W2, b2, g2, be2, mu2, va2, out, N);
}

// round 5
// speedup vs baseline: 1.3461x; 1.3461x over previous
#include <cuda_runtime.h>
#include <cuda_bf16.h>
#include <math.h>
#include <stdint.h>

#define D       256
#define D4      64
#define NMAX    50000
#define BN_EPS  1e-5f
#define STRIDE  72            // padded smem row stride in bf16 (144B)

// persistent scratch (no allocs allowed)
__device__ float          g_agg [(size_t)NMAX * D];
__device__ __nv_bfloat16  g_m_hi[(size_t)NMAX * D];
__device__ __nv_bfloat16  g_m_lo[(size_t)NMAX * D];

// ---------------- warp MMA helpers (portable sm_80+ ISA) --------------------
__device__ __forceinline__ uint32_t smem_u32(const void* p) {
    uint32_t a;
    asm("{ .reg .u64 t; cvta.to.shared.u64 t, %1; cvt.u32.u64 %0, t; }" : "=r"(a) : "l"(p));
    return a;
}
__device__ __forceinline__ void ldsm_x4(uint32_t* r, uint32_t addr) {
    asm volatile("ldmatrix.sync.aligned.m8n8.x4.shared.b16 {%0,%1,%2,%3}, [%4];"
        : "=r"(r[0]), "=r"(r[1]), "=r"(r[2]), "=r"(r[3]) : "r"(addr));
}
__device__ __forceinline__ void mma_bf16(float* c, const uint32_t* a, const uint32_t* b) {
    asm volatile("mma.sync.aligned.m16n8k16.row.col.f32.bf16.bf16.f32 "
        "{%0,%1,%2,%3}, {%4,%5,%6,%7}, {%8,%9}, {%0,%1,%2,%3};"
        : "+f"(c[0]), "+f"(c[1]), "+f"(c[2]), "+f"(c[3])
        : "r"(a[0]), "r"(a[1]), "r"(a[2]), "r"(a[3]), "r"(b[0]), "r"(b[1]));
}
__device__ __forceinline__ void split_bf16(float v, __nv_bfloat16& h, __nv_bfloat16& l) {
    h = __float2bfloat16(v);
    l = __float2bfloat16(v - __bfloat162float(h));
}

// smem layout (bytes): A_hi, A_lo, B_hi, B_lo each 128*STRIDE*2 = 18432
#define SA_HI  0
#define SA_LO  18432
#define SB_HI  36864
#define SB_LO  55296
#define S_SNT  73728              // gemm1: sS[256], sT[256]
#define SM_BYTES (S_SNT + 2048)

// ---------------------------------------------------------------------------
__global__ void zero_agg_kernel(int n4) {
    int i = blockIdx.x * blockDim.x + threadIdx.x;
    if (i < n4)
        reinterpret_cast<float4*>(g_agg)[i] = make_float4(0.f, 0.f, 0.f, 0.f);
}

// scatter: agg[dst] += relu(x[src] + ea)   (edge_index is int32)
__global__ void scatter_kernel(const float* __restrict__ x,
                               const int* __restrict__ ei,
                               const float* __restrict__ ea, int E) {
    long long i = (long long)blockIdx.x * blockDim.x + threadIdx.x;
    int e = (int)(i >> 6), c = (int)(i & 63);
    if (e >= E) return;
    int s = ei[e], d = ei[E + e];
    float4 xv = reinterpret_cast<const float4*>(x)[(size_t)s * D4 + c];
    float4 av = reinterpret_cast<const float4*>(ea)[(size_t)e * D4 + c];
    float4 m;
    m.x = fmaxf(xv.x + av.x, 0.f); m.y = fmaxf(xv.y + av.y, 0.f);
    m.z = fmaxf(xv.z + av.z, 0.f); m.w = fmaxf(xv.w + av.w, 0.f);
    atomicAdd(&reinterpret_cast<float4*>(g_agg)[(size_t)d * D4 + c], m);
}

// ------------- shared mainloop: acc[2][8][4] += A_tile @ B_tile^T ----------
// A,B already staged in smem (hi/lo, padded stride). Warp w: wm=w&3 (m 32),
// wn=w>>2 (n 64). 3-term split: hi*hi + hi*lo + lo*hi.
__device__ __forceinline__ void mma_chunk(uint32_t smb, int lane, int wm, int wn,
                                          float acc[2][8][4]) {
#pragma unroll
    for (int ks = 0; ks < 4; ks++) {
        uint32_t ah[2][4], al[2][4];
#pragma unroll
        for (int mi = 0; mi < 2; mi++) {
            int row = wm * 32 + mi * 16 + (lane & 15);
            int kk  = ks * 16 + ((lane >> 4) << 3);
            uint32_t ad = smb + SA_HI + (uint32_t)(row * STRIDE + kk) * 2;
            ldsm_x4(ah[mi], ad);
            ldsm_x4(al[mi], ad + (SA_LO - SA_HI));
        }
#pragma unroll
        for (int nb = 0; nb < 4; nb++) {
            uint32_t bh[4], bl[4];
            int nrow = wn * 64 + nb * 16 + (lane & 7) + ((lane >> 4) << 3);
            int kk   = ks * 16 + (((lane >> 3) & 1) << 3);
            uint32_t bd = smb + SB_HI + (uint32_t)(nrow * STRIDE + kk) * 2;
            ldsm_x4(bh, bd);
            ldsm_x4(bl, bd + (SB_LO - SB_HI));
#pragma unroll
            for (int mi = 0; mi < 2; mi++) {
#pragma unroll
                for (int hf = 0; hf < 2; hf++) {
                    float* c = acc[mi][nb * 2 + hf];
                    mma_bf16(c, ah[mi], &bh[hf * 2]);
                    mma_bf16(c, ah[mi], &bl[hf * 2]);
                    mma_bf16(c, al[mi], &bh[hf * 2]);
                }
            }
        }
    }
}

// stage W chunk [128 n x 64 k] fp32 -> split bf16 smem
__device__ __forceinline__ void stage_w(char* sm, const float* __restrict__ W,
                                        int n0, int ch, int tid) {
    int r  = tid >> 1;
    int kh = (tid & 1) * 32;
    const float4* src = reinterpret_cast<const float4*>(W + (size_t)(n0 + r) * D + ch * 64 + kh);
#pragma unroll
    for (int q = 0; q < 8; q++) {
        float4 w = src[q];
        float v[4] = {w.x, w.y, w.z, w.w};
        union { uint2 u; __nv_bfloat16 b[4]; } ph, pl;
#pragma unroll
        for (int t = 0; t < 4; t++) split_bf16(v[t], ph.b[t], pl.b[t]);
        uint32_t off = (uint32_t)(r * STRIDE + kh + q * 4) * 2;
        *reinterpret_cast<uint2*>(sm + SB_HI + off) = ph.u;
        *reinterpret_cast<uint2*>(sm + SB_LO + off) = pl.u;
    }
}

// ------------- GEMM1: mid = gelu(bn1(2x+agg) @ W1^T + b1) -------------------
__global__ void __launch_bounds__(256)
gemm1_tc(const float* __restrict__ x, const float* __restrict__ W1,
         const float* __restrict__ b1,
         const float* __restrict__ g1, const float* __restrict__ be1,
         const float* __restrict__ mu1, const float* __restrict__ va1,
         int N) {
    extern __shared__ char sm[];
    uint32_t smb = smem_u32(sm);
    const int tid = threadIdx.x, lane = tid & 31, wid = tid >> 5;
    const int wm = wid & 3, wn = wid >> 2;
    const int m0 = blockIdx.x * 128;
    const int n0 = blockIdx.y * 128;

    float* sS = reinterpret_cast<float*>(sm + S_SNT);
    float* sT = sS + 256;
    if (tid < D) {
        float sc = g1[tid] * rsqrtf(va1[tid] + BN_EPS);
        sS[tid] = sc;
        sT[tid] = be1[tid] - mu1[tid] * sc;
    }
    __syncthreads();

    float acc[2][8][4];
#pragma unroll
    for (int a = 0; a < 2; a++)
#pragma unroll
        for (int b = 0; b < 8; b++)
#pragma unroll
            for (int c = 0; c < 4; c++) acc[a][b][c] = 0.f;

    for (int ch = 0; ch < 4; ch++) {
        // A: bn1(2x+agg) split
        {
            int r  = tid >> 1;
            int kh = (tid & 1) * 32;
            int grow = m0 + r;
#pragma unroll
            for (int q = 0; q < 8; q++) {
                int k  = kh + q * 4;
                int gk = ch * 64 + k;
                float v[4] = {0.f, 0.f, 0.f, 0.f};
                if (grow < N) {
                    float4 xv = *reinterpret_cast<const float4*>(x + (size_t)grow * D + gk);
                    float4 ag = *reinterpret_cast<const float4*>(g_agg + (size_t)grow * D + gk);
                    v[0] = (2.f * xv.x + ag.x) * sS[gk + 0] + sT[gk + 0];
                    v[1] = (2.f * xv.y + ag.y) * sS[gk + 1] + sT[gk + 1];
                    v[2] = (2.f * xv.z + ag.z) * sS[gk + 2] + sT[gk + 2];
                    v[3] = (2.f * xv.w + ag.w) * sS[gk + 3] + sT[gk + 3];
                }
                union { uint2 u; __nv_bfloat16 b[4]; } ph, pl;
#pragma unroll
                for (int t = 0; t < 4; t++) split_bf16(v[t], ph.b[t], pl.b[t]);
                uint32_t off = (uint32_t)(r * STRIDE + k) * 2;
                *reinterpret_cast<uint2*>(sm + SA_HI + off) = ph.u;
                *reinterpret_cast<uint2*>(sm + SA_LO + off) = pl.u;
            }
        }
        stage_w(sm, W1, n0, ch, tid);
        __syncthreads();
        mma_chunk(smb, lane, wm, wn, acc);
        __syncthreads();
    }

    // epilogue: +bias, exact GELU, write mid hi/lo (bf16)
#pragma unroll
    for (int mi = 0; mi < 2; mi++) {
#pragma unroll
        for (int ni = 0; ni < 8; ni++) {
            int col = n0 + wn * 64 + ni * 8 + (lane & 3) * 2;
            float2 bb = *reinterpret_cast<const float2*>(b1 + col);
#pragma unroll
            for (int h = 0; h < 2; h++) {
                int row = m0 + wm * 32 + mi * 16 + (lane >> 2) + h * 8;
                if (row >= N) continue;
                float u0 = acc[mi][ni][h * 2 + 0] + bb.x;
                float u1 = acc[mi][ni][h * 2 + 1] + bb.y;
                float gl0 = 0.5f * u0 * (1.f + erff(u0 * 0.70710678118f));
                float gl1 = 0.5f * u1 * (1.f + erff(u1 * 0.70710678118f));
                union { uint32_t u; __nv_bfloat16 b[2]; } ph, pl;
                split_bf16(gl0, ph.b[0], pl.b[0]);
                split_bf16(gl1, ph.b[1], pl.b[1]);
                *reinterpret_cast<uint32_t*>(g_m_hi + (size_t)row * D + col) = ph.u;
                *reinterpret_cast<uint32_t*>(g_m_lo + (size_t)row * D + col) = pl.u;
            }
        }
    }
}

// ------------- GEMM2: out = bn2((2x+agg) + mid @ W2^T + b2) ------------------
__global__ void __launch_bounds__(256)
gemm2_tc(const float* __restrict__ x, const float* __restrict__ W2,
         const float* __restrict__ b2,
         const float* __restrict__ g2, const float* __restrict__ be2,
         const float* __restrict__ mu2, const float* __restrict__ va2,
         float* __restrict__ out, int N) {
    extern __shared__ char sm[];
    uint32_t smb = smem_u32(sm);
    const int tid = threadIdx.x, lane = tid & 31, wid = tid >> 5;
    const int wm = wid & 3, wn = wid >> 2;
    const int m0 = blockIdx.x * 128;
    const int n0 = blockIdx.y * 128;

    float acc[2][8][4];
#pragma unroll
    for (int a = 0; a < 2; a++)
#pragma unroll
        for (int b = 0; b < 8; b++)
#pragma unroll
            for (int c = 0; c < 4; c++) acc[a][b][c] = 0.f;

    for (int ch = 0; ch < 4; ch++) {
        // A: mid hi/lo straight copy
        {
            int r  = tid >> 1;
            int kh = (tid & 1) * 32;
            int grow = m0 + r;
#pragma unroll
            for (int q = 0; q < 4; q++) {     // 4 x uint4 = 32 bf16
                int k = kh + q * 8;
                uint4 vh = make_uint4(0, 0, 0, 0), vl = vh;
                if (grow < N) {
                    size_t gi = (size_t)grow * D + ch * 64 + k;
                    vh = *reinterpret_cast<const uint4*>(g_m_hi + gi);
                    vl = *reinterpret_cast<const uint4*>(g_m_lo + gi);
                }
                uint32_t off = (uint32_t)(r * STRIDE + k) * 2;
                *reinterpret_cast<uint4*>(sm + SA_HI + off) = vh;
                *reinterpret_cast<uint4*>(sm + SA_LO + off) = vl;
            }
        }
        stage_w(sm, W2, n0, ch, tid);
        __syncthreads();
        mma_chunk(smb, lane, wm, wn, acc);
        __syncthreads();
    }

    // epilogue: f = acc + b2; h = 2x+agg; out = (h+f)*s2 + t2
#pragma unroll
    for (int mi = 0; mi < 2; mi++) {
#pragma unroll
        for (int ni = 0; ni < 8; ni++) {
            int col = n0 + wn * 64 + ni * 8 + (lane & 3) * 2;
            float2 bb = *reinterpret_cast<const float2*>(b2 + col);
            float2 ga = *reinterpret_cast<const float2*>(g2 + col);
            float2 be = *reinterpret_cast<const float2*>(be2 + col);
            float2 mu = *reinterpret_cast<const float2*>(mu2 + col);
            float2 va = *reinterpret_cast<const float2*>(va2 + col);
            float s0 = ga.x * rsqrtf(va.x + BN_EPS), t0 = be.x - mu.x * s0;
            float s1 = ga.y * rsqrtf(va.y + BN_EPS), t1 = be.y - mu.y * s1;
#pragma unroll
            for (int h = 0; h < 2; h++) {
                int row = m0 + wm * 32 + mi * 16 + (lane >> 2) + h * 8;
                if (row >= N) continue;
                size_t gi = (size_t)row * D + col;
                float2 xv = *reinterpret_cast<const float2*>(x + gi);
                float2 ag = *reinterpret_cast<const float2*>(g_agg + gi);
                float h0 = 2.f * xv.x + ag.x, h1 = 2.f * xv.y + ag.y;
                float f0 = acc[mi][ni][h * 2 + 0] + bb.x;
                float f1 = acc[mi][ni][h * 2 + 1] + bb.y;
                float2 o;
                o.x = (h0 + f0) * s0 + t0;
                o.y = (h1 + f1) * s1 + t1;
                *reinterpret_cast<float2*>(out + gi) = o;
            }
        }
    }
}

// ---------------------------------------------------------------------------
extern "C" void kernel_launch(void* const* d_in, const int* in_sizes, int n_in,
                              void* d_out, int out_size) {
    const float* x   = (const float*)d_in[0];
    const int*   ei  = (const int*)d_in[1];
    const float* ea  = (const float*)d_in[2];
    const float* W1  = (const float*)d_in[3];
    const float* b1  = (const float*)d_in[4];
    const float* W2  = (const float*)d_in[5];
    const float* b2  = (const float*)d_in[6];
    const float* g1  = (const float*)d_in[7];
    const float* be1 = (const float*)d_in[8];
    const float* mu1 = (const float*)d_in[9];
    const float* va1 = (const float*)d_in[10];
    const float* g2  = (const float*)d_in[11];
    const float* be2 = (const float*)d_in[12];
    const float* mu2 = (const float*)d_in[13];
    const float* va2 = (const float*)d_in[14];
    float*       out = (float*)d_out;

    int N = in_sizes[0] / D;
    int E = in_sizes[2] / D;

    cudaFuncSetAttribute(gemm1_tc, cudaFuncAttributeMaxDynamicSharedMemorySize, SM_BYTES);
    cudaFuncSetAttribute(gemm2_tc, cudaFuncAttributeMaxDynamicSharedMemorySize, SM_BYTES);

    int n4 = N * D4;
    zero_agg_kernel<<<(n4 + 255) / 256, 256>>>(n4);

    long long total = (long long)E * 64;
    scatter_kernel<<<(int)((total + 255) / 256), 256>>>(x, ei, ea, E);

    dim3 grid((N + 127) / 128, 2);
    gemm1_tc<<<grid, 256, SM_BYTES>>>(x, W1, b1, g1, be1, mu1, va1, N);
    gemm2_tc<<<grid, 256, SM_BYTES>>>(x, W2, b2, g2, be2, mu2, va2, out, N);
}

// round 6
// speedup vs baseline: 1.4276x; 1.0605x over previous
#include <cuda_runtime.h>
#include <cuda_bf16.h>
#include <math.h>
#include <stdint.h>

#define D       256
#define D4      64
#define NMAX    50000
#define BN_EPS  1e-5f
#define STRIDE  72            // padded smem row stride in bf16 (144B)

// persistent scratch (no allocs allowed)
__device__ float          g_agg [(size_t)NMAX * D];
__device__ __nv_bfloat16  g_a_hi[(size_t)NMAX * D];
__device__ __nv_bfloat16  g_a_lo[(size_t)NMAX * D];
__device__ __nv_bfloat16  g_m_hi[(size_t)NMAX * D];
__device__ __nv_bfloat16  g_m_lo[(size_t)NMAX * D];
__device__ __nv_bfloat16  g_w1_hi[D * D], g_w1_lo[D * D];
__device__ __nv_bfloat16  g_w2_hi[D * D], g_w2_lo[D * D];

// ---------------- helpers ----------------------------------------------------
__device__ __forceinline__ uint32_t smem_u32(const void* p) {
    uint32_t a;
    asm("{ .reg .u64 t; cvta.to.shared.u64 t, %1; cvt.u32.u64 %0, t; }" : "=r"(a) : "l"(p));
    return a;
}
__device__ __forceinline__ void ldsm_x4(uint32_t* r, uint32_t addr) {
    asm volatile("ldmatrix.sync.aligned.m8n8.x4.shared.b16 {%0,%1,%2,%3}, [%4];"
        : "=r"(r[0]), "=r"(r[1]), "=r"(r[2]), "=r"(r[3]) : "r"(addr));
}
__device__ __forceinline__ void mma_bf16(float* c, const uint32_t* a, const uint32_t* b) {
    asm volatile("mma.sync.aligned.m16n8k16.row.col.f32.bf16.bf16.f32 "
        "{%0,%1,%2,%3}, {%4,%5,%6,%7}, {%8,%9}, {%0,%1,%2,%3};"
        : "+f"(c[0]), "+f"(c[1]), "+f"(c[2]), "+f"(c[3])
        : "r"(a[0]), "r"(a[1]), "r"(a[2]), "r"(a[3]), "r"(b[0]), "r"(b[1]));
}
__device__ __forceinline__ void split_bf16(float v, __nv_bfloat16& h, __nv_bfloat16& l) {
    h = __float2bfloat16(v);
    l = __float2bfloat16(v - __bfloat162float(h));
}
__device__ __forceinline__ void cp16(uint32_t saddr, const void* gaddr) {
    asm volatile("cp.async.cg.shared.global [%0], [%1], 16;" :: "r"(saddr), "l"(gaddr));
}
#define CP_COMMIT() asm volatile("cp.async.commit_group;" ::: "memory")
#define CP_WAIT(n)  asm volatile("cp.async.wait_group %0;" :: "n"(n) : "memory")

// per-buffer smem layout (bytes): A_hi, A_lo, B_hi, B_lo each 128*STRIDE*2=18432
#define T_AHI  0
#define T_ALO  18432
#define T_BHI  36864
#define T_BLO  55296
#define BUF_BYTES 73728
#define SM_BYTES  (2 * BUF_BYTES)

// ---------------------------------------------------------------------------
__global__ void zero_agg_kernel(int n4) {
    int i = blockIdx.x * blockDim.x + threadIdx.x;
    if (i < n4)
        reinterpret_cast<float4*>(g_agg)[i] = make_float4(0.f, 0.f, 0.f, 0.f);
}

// scatter: agg[dst] += relu(x[src] + ea)   (edge_index is int32)
__global__ void scatter_kernel(const float* __restrict__ x,
                               const int* __restrict__ ei,
                               const float* __restrict__ ea, int E) {
    long long i = (long long)blockIdx.x * blockDim.x + threadIdx.x;
    int e = (int)(i >> 6), c = (int)(i & 63);
    if (e >= E) return;
    int s = ei[e], d = ei[E + e];
    float4 xv = reinterpret_cast<const float4*>(x)[(size_t)s * D4 + c];
    float4 av = reinterpret_cast<const float4*>(ea)[(size_t)e * D4 + c];
    float4 m;
    m.x = fmaxf(xv.x + av.x, 0.f); m.y = fmaxf(xv.y + av.y, 0.f);
    m.z = fmaxf(xv.z + av.z, 0.f); m.w = fmaxf(xv.w + av.w, 0.f);
    atomicAdd(&reinterpret_cast<float4*>(g_agg)[(size_t)d * D4 + c], m);
}

// split both weight matrices into bf16 hi/lo (once per launch, cheap)
__global__ void split_w_kernel(const float* __restrict__ W1,
                               const float* __restrict__ W2) {
    int i = blockIdx.x * blockDim.x + threadIdx.x;
    if (i >= 2 * (D * D / 4)) return;
    bool second = i >= (D * D / 4);
    int j = second ? i - D * D / 4 : i;
    float4 w = reinterpret_cast<const float4*>(second ? W2 : W1)[j];
    __nv_bfloat16* hi = second ? g_w2_hi : g_w1_hi;
    __nv_bfloat16* lo = second ? g_w2_lo : g_w1_lo;
    float v[4] = {w.x, w.y, w.z, w.w};
    union { uint2 u; __nv_bfloat16 b[4]; } ph, pl;
#pragma unroll
    for (int t = 0; t < 4; t++) split_bf16(v[t], ph.b[t], pl.b[t]);
    reinterpret_cast<uint2*>(hi)[j] = ph.u;
    reinterpret_cast<uint2*>(lo)[j] = pl.u;
}

// prep: a = bn1(2x + agg), split to bf16 hi/lo
__global__ void prep_a_kernel(const float* __restrict__ x,
                              const float* __restrict__ g1, const float* __restrict__ be1,
                              const float* __restrict__ mu1, const float* __restrict__ va1,
                              int N) {
    __shared__ float sS[D], sT[D];
    if (threadIdx.x < D) {
        float sc = g1[threadIdx.x] * rsqrtf(va1[threadIdx.x] + BN_EPS);
        sS[threadIdx.x] = sc;
        sT[threadIdx.x] = be1[threadIdx.x] - mu1[threadIdx.x] * sc;
    }
    __syncthreads();
    long long i = (long long)blockIdx.x * blockDim.x + threadIdx.x;
    if (i >= (long long)N * D4) return;
    int c4 = (int)(i & 63);
    float4 xv = reinterpret_cast<const float4*>(x)[i];
    float4 ag = reinterpret_cast<const float4*>(g_agg)[i];
    float v[4];
    v[0] = (2.f * xv.x + ag.x) * sS[c4 * 4 + 0] + sT[c4 * 4 + 0];
    v[1] = (2.f * xv.y + ag.y) * sS[c4 * 4 + 1] + sT[c4 * 4 + 1];
    v[2] = (2.f * xv.z + ag.z) * sS[c4 * 4 + 2] + sT[c4 * 4 + 2];
    v[3] = (2.f * xv.w + ag.w) * sS[c4 * 4 + 3] + sT[c4 * 4 + 3];
    union { uint2 u; __nv_bfloat16 b[4]; } ph, pl;
#pragma unroll
    for (int t = 0; t < 4; t++) split_bf16(v[t], ph.b[t], pl.b[t]);
    reinterpret_cast<uint2*>(g_a_hi)[i] = ph.u;
    reinterpret_cast<uint2*>(g_a_lo)[i] = pl.u;
}

// ------------- stage one k-chunk (all-bf16 sources) via cp.async ------------
// thread t: row = t>>1, 64-byte half = t&1; 4x 16B per tile, 4 tiles.
__device__ __forceinline__ void stage_chunk(uint32_t sbase,
                                            const __nv_bfloat16* __restrict__ Ahi,
                                            const __nv_bfloat16* __restrict__ Alo,
                                            const __nv_bfloat16* __restrict__ Whi,
                                            const __nv_bfloat16* __restrict__ Wlo,
                                            int m0, int n0, int ch, int N, int tid) {
    int r  = tid >> 1;
    int kh = (tid & 1) * 32;                       // element offset within chunk
    int arow = m0 + r; if (arow >= N) arow = 0;    // clamp: garbage rows unused
    size_t  agi = (size_t)arow * D + ch * 64 + kh;
    size_t  bgi = (size_t)(n0 + r) * D + ch * 64 + kh;
    uint32_t soff = (uint32_t)(r * STRIDE + kh) * 2;
#pragma unroll
    for (int q = 0; q < 4; q++) {
        cp16(sbase + T_AHI + soff + q * 16, Ahi + agi + q * 8);
        cp16(sbase + T_ALO + soff + q * 16, Alo + agi + q * 8);
        cp16(sbase + T_BHI + soff + q * 16, Whi + bgi + q * 8);
        cp16(sbase + T_BLO + soff + q * 16, Wlo + bgi + q * 8);
    }
}

// ------------- MMA over one staged chunk ------------------------------------
__device__ __forceinline__ void mma_chunk(uint32_t base, int lane, int wm, int wn,
                                          float acc[2][8][4]) {
#pragma unroll
    for (int ks = 0; ks < 4; ks++) {
        uint32_t ah[2][4], al[2][4];
#pragma unroll
        for (int mi = 0; mi < 2; mi++) {
            int row = wm * 32 + mi * 16 + (lane & 15);
            int kk  = ks * 16 + ((lane >> 4) << 3);
            uint32_t ad = base + T_AHI + (uint32_t)(row * STRIDE + kk) * 2;
            ldsm_x4(ah[mi], ad);
            ldsm_x4(al[mi], ad + (T_ALO - T_AHI));
        }
#pragma unroll
        for (int nb = 0; nb < 4; nb++) {
            uint32_t bh[4], bl[4];
            int nrow = wn * 64 + nb * 16 + (lane & 7) + ((lane >> 4) << 3);
            int kk   = ks * 16 + (((lane >> 3) & 1) << 3);
            uint32_t bd = base + T_BHI + (uint32_t)(nrow * STRIDE + kk) * 2;
            ldsm_x4(bh, bd);
            ldsm_x4(bl, bd + (T_BLO - T_BHI));
#pragma unroll
            for (int mi = 0; mi < 2; mi++) {
#pragma unroll
                for (int hf = 0; hf < 2; hf++) {
                    float* c = acc[mi][nb * 2 + hf];
                    mma_bf16(c, ah[mi], &bh[hf * 2]);
                    mma_bf16(c, ah[mi], &bl[hf * 2]);
                    mma_bf16(c, al[mi], &bh[hf * 2]);
                }
            }
        }
    }
}

// pipelined mainloop: double-buffered cp.async over 4 k-chunks
__device__ __forceinline__ void gemm_mainloop(uint32_t smb,
                                              const __nv_bfloat16* Ahi, const __nv_bfloat16* Alo,
                                              const __nv_bfloat16* Whi, const __nv_bfloat16* Wlo,
                                              int m0, int n0, int N, int tid,
                                              int lane, int wm, int wn,
                                              float acc[2][8][4]) {
    stage_chunk(smb, Ahi, Alo, Whi, Wlo, m0, n0, 0, N, tid);
    CP_COMMIT();
#pragma unroll
    for (int ch = 0; ch < 4; ch++) {
        if (ch < 3) {
            stage_chunk(smb + ((ch + 1) & 1) * BUF_BYTES, Ahi, Alo, Whi, Wlo,
                        m0, n0, ch + 1, N, tid);
            CP_COMMIT();
            CP_WAIT(1);
        } else {
            CP_WAIT(0);
        }
        __syncthreads();
        mma_chunk(smb + (ch & 1) * BUF_BYTES, lane, wm, wn, acc);
        __syncthreads();
    }
}

// ------------- GEMM1: mid = gelu(a @ W1^T + b1), split to bf16 --------------
__global__ void __launch_bounds__(256)
gemm1_tc(const float* __restrict__ b1, int N) {
    extern __shared__ char sm[];
    uint32_t smb = smem_u32(sm);
    const int tid = threadIdx.x, lane = tid & 31, wid = tid >> 5;
    const int wm = wid & 3, wn = wid >> 2;
    const int m0 = blockIdx.x * 128;
    const int n0 = blockIdx.y * 128;

    float acc[2][8][4];
#pragma unroll
    for (int a = 0; a < 2; a++)
#pragma unroll
        for (int b = 0; b < 8; b++)
#pragma unroll
            for (int c = 0; c < 4; c++) acc[a][b][c] = 0.f;

    gemm_mainloop(smb, g_a_hi, g_a_lo, g_w1_hi, g_w1_lo, m0, n0, N, tid, lane, wm, wn, acc);

#pragma unroll
    for (int mi = 0; mi < 2; mi++) {
#pragma unroll
        for (int ni = 0; ni < 8; ni++) {
            int col = n0 + wn * 64 + ni * 8 + (lane & 3) * 2;
            float2 bb = *reinterpret_cast<const float2*>(b1 + col);
#pragma unroll
            for (int h = 0; h < 2; h++) {
                int row = m0 + wm * 32 + mi * 16 + (lane >> 2) + h * 8;
                if (row >= N) continue;
                float u0 = acc[mi][ni][h * 2 + 0] + bb.x;
                float u1 = acc[mi][ni][h * 2 + 1] + bb.y;
                float gl0 = 0.5f * u0 * (1.f + erff(u0 * 0.70710678118f));
                float gl1 = 0.5f * u1 * (1.f + erff(u1 * 0.70710678118f));
                union { uint32_t u; __nv_bfloat16 b[2]; } ph, pl;
                split_bf16(gl0, ph.b[0], pl.b[0]);
                split_bf16(gl1, ph.b[1], pl.b[1]);
                *reinterpret_cast<uint32_t*>(g_m_hi + (size_t)row * D + col) = ph.u;
                *reinterpret_cast<uint32_t*>(g_m_lo + (size_t)row * D + col) = pl.u;
            }
        }
    }
}

// ------------- GEMM2: out = bn2((2x+agg) + mid @ W2^T + b2) ------------------
__global__ void __launch_bounds__(256)
gemm2_tc(const float* __restrict__ x,
         const float* __restrict__ b2,
         const float* __restrict__ g2, const float* __restrict__ be2,
         const float* __restrict__ mu2, const float* __restrict__ va2,
         float* __restrict__ out, int N) {
    extern __shared__ char sm[];
    uint32_t smb = smem_u32(sm);
    const int tid = threadIdx.x, lane = tid & 31, wid = tid >> 5;
    const int wm = wid & 3, wn = wid >> 2;
    const int m0 = blockIdx.x * 128;
    const int n0 = blockIdx.y * 128;

    float acc[2][8][4];
#pragma unroll
    for (int a = 0; a < 2; a++)
#pragma unroll
        for (int b = 0; b < 8; b++)
#pragma unroll
            for (int c = 0; c < 4; c++) acc[a][b][c] = 0.f;

    gemm_mainloop(smb, g_m_hi, g_m_lo, g_w2_hi, g_w2_lo, m0, n0, N, tid, lane, wm, wn, acc);

#pragma unroll
    for (int mi = 0; mi < 2; mi++) {
#pragma unroll
        for (int ni = 0; ni < 8; ni++) {
            int col = n0 + wn * 64 + ni * 8 + (lane & 3) * 2;
            float2 bb = *reinterpret_cast<const float2*>(b2 + col);
            float2 ga = *reinterpret_cast<const float2*>(g2 + col);
            float2 be = *reinterpret_cast<const float2*>(be2 + col);
            float2 mu = *reinterpret_cast<const float2*>(mu2 + col);
            float2 va = *reinterpret_cast<const float2*>(va2 + col);
            float s0 = ga.x * rsqrtf(va.x + BN_EPS), t0 = be.x - mu.x * s0;
            float s1 = ga.y * rsqrtf(va.y + BN_EPS), t1 = be.y - mu.y * s1;
#pragma unroll
            for (int h = 0; h < 2; h++) {
                int row = m0 + wm * 32 + mi * 16 + (lane >> 2) + h * 8;
                if (row >= N) continue;
                size_t gi = (size_t)row * D + col;
                float2 xv = *reinterpret_cast<const float2*>(x + gi);
                float2 ag = *reinterpret_cast<const float2*>(g_agg + gi);
                float h0 = 2.f * xv.x + ag.x, h1 = 2.f * xv.y + ag.y;
                float f0 = acc[mi][ni][h * 2 + 0] + bb.x;
                float f1 = acc[mi][ni][h * 2 + 1] + bb.y;
                float2 o;
                o.x = (h0 + f0) * s0 + t0;
                o.y = (h1 + f1) * s1 + t1;
                *reinterpret_cast<float2*>(out + gi) = o;
            }
        }
    }
}

// ---------------------------------------------------------------------------
extern "C" void kernel_launch(void* const* d_in, const int* in_sizes, int n_in,
                              void* d_out, int out_size) {
    const float* x   = (const float*)d_in[0];
    const int*   ei  = (const int*)d_in[1];
    const float* ea  = (const float*)d_in[2];
    const float* W1  = (const float*)d_in[3];
    const float* b1  = (const float*)d_in[4];
    const float* W2  = (const float*)d_in[5];
    const float* b2  = (const float*)d_in[6];
    const float* g1  = (const float*)d_in[7];
    const float* be1 = (const float*)d_in[8];
    const float* mu1 = (const float*)d_in[9];
    const float* va1 = (const float*)d_in[10];
    const float* g2  = (const float*)d_in[11];
    const float* be2 = (const float*)d_in[12];
    const float* mu2 = (const float*)d_in[13];
    const float* va2 = (const float*)d_in[14];
    float*       out = (float*)d_out;

    int N = in_sizes[0] / D;
    int E = in_sizes[2] / D;

    cudaFuncSetAttribute(gemm1_tc, cudaFuncAttributeMaxDynamicSharedMemorySize, SM_BYTES);
    cudaFuncSetAttribute(gemm2_tc, cudaFuncAttributeMaxDynamicSharedMemorySize, SM_BYTES);

    int n4 = N * D4;
    zero_agg_kernel<<<(n4 + 255) / 256, 256>>>(n4);

    long long total = (long long)E * 64;
    scatter_kernel<<<(int)((total + 255) / 256), 256>>>(x, ei, ea, E);

    split_w_kernel<<<(2 * (D * D / 4) + 255) / 256, 256>>>(W1, W2);
    prep_a_kernel<<<(int)(((long long)N * D4 + 255) / 256), 256>>>(x, g1, be1, mu1, va1, N);

    dim3 grid((N + 127) / 128, 2);
    gemm1_tc<<<grid, 256, SM_BYTES>>>(b1, N);
    gemm2_tc<<<grid, 256, SM_BYTES>>>(x, b2, g2, be2, mu2, va2, out, N);
}

// round 7
// speedup vs baseline: 1.5743x; 1.1028x over previous
#include <cuda_runtime.h>
#include <cuda_bf16.h>
#include <math.h>
#include <stdint.h>

#define D       256
#define D4      64
#define NMAX    50000
#define EMAX    301000
#define BN_EPS  1e-5f
#define KCH     32
#define NCHUNK  8
#define STRIDE  40            // padded smem row stride in bf16 (80B) for k=32

// persistent scratch (no allocs allowed)
__device__ int            g_cnt[NMAX], g_off[NMAX], g_cur[NMAX];
__device__ int            g_idx[EMAX];
__device__ float          g_h  [(size_t)NMAX * D];
__device__ __nv_bfloat16  g_a_hi[(size_t)NMAX * D];
__device__ __nv_bfloat16  g_a_lo[(size_t)NMAX * D];
__device__ __nv_bfloat16  g_m_hi[(size_t)NMAX * D];
__device__ __nv_bfloat16  g_m_lo[(size_t)NMAX * D];
__device__ __nv_bfloat16  g_w1_hi[D * D], g_w1_lo[D * D];
__device__ __nv_bfloat16  g_w2_hi[D * D], g_w2_lo[D * D];

// ---------------- helpers ----------------------------------------------------
__device__ __forceinline__ uint32_t smem_u32(const void* p) {
    uint32_t a;
    asm("{ .reg .u64 t; cvta.to.shared.u64 t, %1; cvt.u32.u64 %0, t; }" : "=r"(a) : "l"(p));
    return a;
}
__device__ __forceinline__ void ldsm_x4(uint32_t* r, uint32_t addr) {
    asm volatile("ldmatrix.sync.aligned.m8n8.x4.shared.b16 {%0,%1,%2,%3}, [%4];"
        : "=r"(r[0]), "=r"(r[1]), "=r"(r[2]), "=r"(r[3]) : "r"(addr));
}
__device__ __forceinline__ void mma_bf16(float* c, const uint32_t* a, const uint32_t* b) {
    asm volatile("mma.sync.aligned.m16n8k16.row.col.f32.bf16.bf16.f32 "
        "{%0,%1,%2,%3}, {%4,%5,%6,%7}, {%8,%9}, {%0,%1,%2,%3};"
        : "+f"(c[0]), "+f"(c[1]), "+f"(c[2]), "+f"(c[3])
        : "r"(a[0]), "r"(a[1]), "r"(a[2]), "r"(a[3]), "r"(b[0]), "r"(b[1]));
}
__device__ __forceinline__ void split_bf16(float v, __nv_bfloat16& h, __nv_bfloat16& l) {
    h = __float2bfloat16(v);
    l = __float2bfloat16(v - __bfloat162float(h));
}
__device__ __forceinline__ void cp16(uint32_t saddr, const void* gaddr) {
    asm volatile("cp.async.cg.shared.global [%0], [%1], 16;" :: "r"(saddr), "l"(gaddr));
}
#define CP_COMMIT() asm volatile("cp.async.commit_group;" ::: "memory")
#define CP_WAIT(n)  asm volatile("cp.async.wait_group %0;" :: "n"(n) : "memory")

// per-buffer smem layout (bytes): four 128 x 32 bf16 tiles, stride 40
#define T_AHI  0
#define T_ALO  10240
#define T_BHI  20480
#define T_BLO  30720
#define BUF_BYTES 40960
#define SM_BYTES  (2 * BUF_BYTES)      // 80 KB -> 2 CTAs/SM

// ====================== CSR build (no float atomics) ========================
__global__ void zero_cnt_kernel(int N) {
    int i = blockIdx.x * blockDim.x + threadIdx.x;
    if (i < N) g_cnt[i] = 0;
}
__global__ void count_kernel(const int* __restrict__ ei, int E) {
    int i = blockIdx.x * blockDim.x + threadIdx.x;
    if (i < E) atomicAdd(&g_cnt[ei[E + i]], 1);
}
// single-block exclusive scan over N counts -> g_off, g_cur
__global__ void scan_kernel(int N) {
    __shared__ int part[1024];
    int tid = threadIdx.x;
    int per = (N + 1023) >> 10;
    int lo = tid * per;
    int hi = lo + per; if (hi > N) hi = N;
    int s = 0;
    for (int i = lo; i < hi; i++) s += g_cnt[i];
    part[tid] = s;
    __syncthreads();
    for (int o = 1; o < 1024; o <<= 1) {
        int v = (tid >= o) ? part[tid - o] : 0;
        __syncthreads();
        part[tid] += v;
        __syncthreads();
    }
    int run = (tid == 0) ? 0 : part[tid - 1];
    for (int i = lo; i < hi; i++) {
        g_off[i] = run;
        g_cur[i] = run;
        run += g_cnt[i];
    }
}
__global__ void fill_kernel(const int* __restrict__ ei, int E) {
    int i = blockIdx.x * blockDim.x + threadIdx.x;
    if (i < E) {
        int d = ei[E + i];
        int p = atomicAdd(&g_cur[d], 1);
        g_idx[p] = i;
    }
}

// gather: agg = sum relu(x[src]+ea); h = 2x+agg -> g_h; bn1(h) split -> g_a
__global__ void gather_kernel(const float* __restrict__ x,
                              const int* __restrict__ ei,
                              const float* __restrict__ ea,
                              const float* __restrict__ g1, const float* __restrict__ be1,
                              const float* __restrict__ mu1, const float* __restrict__ va1,
                              int N, int E) {
    int t = blockIdx.x * blockDim.x + threadIdx.x;
    int node = t >> 6, c = t & 63;
    if (node >= N) return;
    int off = g_off[node], deg = g_cnt[node];

    float4 sum = make_float4(0.f, 0.f, 0.f, 0.f);
    for (int j = 0; j < deg; j++) {
        int e = g_idx[off + j];
        int s = ei[e];
        float4 xv = reinterpret_cast<const float4*>(x)[(size_t)s * D4 + c];
        float4 av = reinterpret_cast<const float4*>(ea)[(size_t)e * D4 + c];
        sum.x += fmaxf(xv.x + av.x, 0.f);
        sum.y += fmaxf(xv.y + av.y, 0.f);
        sum.z += fmaxf(xv.z + av.z, 0.f);
        sum.w += fmaxf(xv.w + av.w, 0.f);
    }
    float4 xn = reinterpret_cast<const float4*>(x)[(size_t)node * D4 + c];
    float4 h;
    h.x = 2.f * xn.x + sum.x; h.y = 2.f * xn.y + sum.y;
    h.z = 2.f * xn.z + sum.z; h.w = 2.f * xn.w + sum.w;
    reinterpret_cast<float4*>(g_h)[(size_t)node * D4 + c] = h;

    float4 ga = reinterpret_cast<const float4*>(g1)[c];
    float4 va = reinterpret_cast<const float4*>(va1)[c];
    float4 be = reinterpret_cast<const float4*>(be1)[c];
    float4 mu = reinterpret_cast<const float4*>(mu1)[c];
    float v[4];
    float sc;
    sc = ga.x * rsqrtf(va.x + BN_EPS); v[0] = h.x * sc + (be.x - mu.x * sc);
    sc = ga.y * rsqrtf(va.y + BN_EPS); v[1] = h.y * sc + (be.y - mu.y * sc);
    sc = ga.z * rsqrtf(va.z + BN_EPS); v[2] = h.z * sc + (be.z - mu.z * sc);
    sc = ga.w * rsqrtf(va.w + BN_EPS); v[3] = h.w * sc + (be.w - mu.w * sc);
    union { uint2 u; __nv_bfloat16 b[4]; } ph, pl;
#pragma unroll
    for (int q = 0; q < 4; q++) split_bf16(v[q], ph.b[q], pl.b[q]);
    reinterpret_cast<uint2*>(g_a_hi)[(size_t)node * D4 + c] = ph.u;
    reinterpret_cast<uint2*>(g_a_lo)[(size_t)node * D4 + c] = pl.u;
}

// split both weight matrices into bf16 hi/lo (once per launch, cheap)
__global__ void split_w_kernel(const float* __restrict__ W1,
                               const float* __restrict__ W2) {
    int i = blockIdx.x * blockDim.x + threadIdx.x;
    if (i >= 2 * (D * D / 4)) return;
    bool second = i >= (D * D / 4);
    int j = second ? i - D * D / 4 : i;
    float4 w = reinterpret_cast<const float4*>(second ? W2 : W1)[j];
    __nv_bfloat16* hi = second ? g_w2_hi : g_w1_hi;
    __nv_bfloat16* lo = second ? g_w2_lo : g_w1_lo;
    float v[4] = {w.x, w.y, w.z, w.w};
    union { uint2 u; __nv_bfloat16 b[4]; } ph, pl;
#pragma unroll
    for (int t = 0; t < 4; t++) split_bf16(v[t], ph.b[t], pl.b[t]);
    reinterpret_cast<uint2*>(hi)[j] = ph.u;
    reinterpret_cast<uint2*>(lo)[j] = pl.u;
}

// ====================== GEMM machinery (k=32 chunks) ========================
__device__ __forceinline__ void stage_chunk(uint32_t sbase,
                                            const __nv_bfloat16* __restrict__ Ahi,
                                            const __nv_bfloat16* __restrict__ Alo,
                                            const __nv_bfloat16* __restrict__ Whi,
                                            const __nv_bfloat16* __restrict__ Wlo,
                                            int m0, int n0, int ch, int N, int tid) {
    int r  = tid >> 1;
    int kh = (tid & 1) * 16;                       // elements (32B half-row)
    int arow = m0 + r; if (arow >= N) arow = 0;    // clamp: garbage rows unused
    size_t  agi = (size_t)arow * D + ch * KCH + kh;
    size_t  bgi = (size_t)(n0 + r) * D + ch * KCH + kh;
    uint32_t soff = (uint32_t)(r * STRIDE + kh) * 2;
#pragma unroll
    for (int q = 0; q < 2; q++) {
        cp16(sbase + T_AHI + soff + q * 16, Ahi + agi + q * 8);
        cp16(sbase + T_ALO + soff + q * 16, Alo + agi + q * 8);
        cp16(sbase + T_BHI + soff + q * 16, Whi + bgi + q * 8);
        cp16(sbase + T_BLO + soff + q * 16, Wlo + bgi + q * 8);
    }
}

__device__ __forceinline__ void mma_chunk(uint32_t base, int lane, int wm, int wn,
                                          float acc[2][8][4]) {
#pragma unroll
    for (int ks = 0; ks < 2; ks++) {
        uint32_t ah[2][4], al[2][4];
#pragma unroll
        for (int mi = 0; mi < 2; mi++) {
            int row = wm * 32 + mi * 16 + (lane & 15);
            int kk  = ks * 16 + ((lane >> 4) << 3);
            uint32_t ad = base + T_AHI + (uint32_t)(row * STRIDE + kk) * 2;
            ldsm_x4(ah[mi], ad);
            ldsm_x4(al[mi], ad + (T_ALO - T_AHI));
        }
#pragma unroll
        for (int nb = 0; nb < 4; nb++) {
            uint32_t bh[4], bl[4];
            int nrow = wn * 64 + nb * 16 + (lane & 7) + ((lane >> 4) << 3);
            int kk   = ks * 16 + (((lane >> 3) & 1) << 3);
            uint32_t bd = base + T_BHI + (uint32_t)(nrow * STRIDE + kk) * 2;
            ldsm_x4(bh, bd);
            ldsm_x4(bl, bd + (T_BLO - T_BHI));
#pragma unroll
            for (int mi = 0; mi < 2; mi++) {
#pragma unroll
                for (int hf = 0; hf < 2; hf++) {
                    float* c = acc[mi][nb * 2 + hf];
                    mma_bf16(c, ah[mi], &bh[hf * 2]);
                    mma_bf16(c, ah[mi], &bl[hf * 2]);
                    mma_bf16(c, al[mi], &bh[hf * 2]);
                }
            }
        }
    }
}

__device__ __forceinline__ void gemm_mainloop(uint32_t smb,
                                              const __nv_bfloat16* Ahi, const __nv_bfloat16* Alo,
                                              const __nv_bfloat16* Whi, const __nv_bfloat16* Wlo,
                                              int m0, int n0, int N, int tid,
                                              int lane, int wm, int wn,
                                              float acc[2][8][4]) {
    stage_chunk(smb, Ahi, Alo, Whi, Wlo, m0, n0, 0, N, tid);
    CP_COMMIT();
#pragma unroll
    for (int ch = 0; ch < NCHUNK; ch++) {
        if (ch < NCHUNK - 1) {
            stage_chunk(smb + ((ch + 1) & 1) * BUF_BYTES, Ahi, Alo, Whi, Wlo,
                        m0, n0, ch + 1, N, tid);
            CP_COMMIT();
            CP_WAIT(1);
        } else {
            CP_WAIT(0);
        }
        __syncthreads();
        mma_chunk(smb + (ch & 1) * BUF_BYTES, lane, wm, wn, acc);
        __syncthreads();
    }
}

// ------------- GEMM1: mid = gelu(a @ W1^T + b1), split to bf16 --------------
__global__ void __launch_bounds__(256, 2)
gemm1_tc(const float* __restrict__ b1, int N) {
    extern __shared__ char sm[];
    uint32_t smb = smem_u32(sm);
    const int tid = threadIdx.x, lane = tid & 31, wid = tid >> 5;
    const int wm = wid & 3, wn = wid >> 2;
    const int m0 = blockIdx.x * 128;
    const int n0 = blockIdx.y * 128;

    float acc[2][8][4];
#pragma unroll
    for (int a = 0; a < 2; a++)
#pragma unroll
        for (int b = 0; b < 8; b++)
#pragma unroll
            for (int c = 0; c < 4; c++) acc[a][b][c] = 0.f;

    gemm_mainloop(smb, g_a_hi, g_a_lo, g_w1_hi, g_w1_lo, m0, n0, N, tid, lane, wm, wn, acc);

#pragma unroll
    for (int mi = 0; mi < 2; mi++) {
#pragma unroll
        for (int ni = 0; ni < 8; ni++) {
            int col = n0 + wn * 64 + ni * 8 + (lane & 3) * 2;
            float2 bb = *reinterpret_cast<const float2*>(b1 + col);
#pragma unroll
            for (int h = 0; h < 2; h++) {
                int row = m0 + wm * 32 + mi * 16 + (lane >> 2) + h * 8;
                if (row >= N) continue;
                float u0 = acc[mi][ni][h * 2 + 0] + bb.x;
                float u1 = acc[mi][ni][h * 2 + 1] + bb.y;
                float gl0 = 0.5f * u0 * (1.f + erff(u0 * 0.70710678118f));
                float gl1 = 0.5f * u1 * (1.f + erff(u1 * 0.70710678118f));
                union { uint32_t u; __nv_bfloat16 b[2]; } ph, pl;
                split_bf16(gl0, ph.b[0], pl.b[0]);
                split_bf16(gl1, ph.b[1], pl.b[1]);
                *reinterpret_cast<uint32_t*>(g_m_hi + (size_t)row * D + col) = ph.u;
                *reinterpret_cast<uint32_t*>(g_m_lo + (size_t)row * D + col) = pl.u;
            }
        }
    }
}

// ------------- GEMM2: out = bn2(h + mid @ W2^T + b2) -------------------------
__global__ void __launch_bounds__(256, 2)
gemm2_tc(const float* __restrict__ b2,
         const float* __restrict__ g2, const float* __restrict__ be2,
         const float* __restrict__ mu2, const float* __restrict__ va2,
         float* __restrict__ out, int N) {
    extern __shared__ char sm[];
    uint32_t smb = smem_u32(sm);
    const int tid = threadIdx.x, lane = tid & 31, wid = tid >> 5;
    const int wm = wid & 3, wn = wid >> 2;
    const int m0 = blockIdx.x * 128;
    const int n0 = blockIdx.y * 128;

    float acc[2][8][4];
#pragma unroll
    for (int a = 0; a < 2; a++)
#pragma unroll
        for (int b = 0; b < 8; b++)
#pragma unroll
            for (int c = 0; c < 4; c++) acc[a][b][c] = 0.f;

    gemm_mainloop(smb, g_m_hi, g_m_lo, g_w2_hi, g_w2_lo, m0, n0, N, tid, lane, wm, wn, acc);

#pragma unroll
    for (int mi = 0; mi < 2; mi++) {
#pragma unroll
        for (int ni = 0; ni < 8; ni++) {
            int col = n0 + wn * 64 + ni * 8 + (lane & 3) * 2;
            float2 bb = *reinterpret_cast<const float2*>(b2 + col);
            float2 ga = *reinterpret_cast<const float2*>(g2 + col);
            float2 be = *reinterpret_cast<const float2*>(be2 + col);
            float2 mu = *reinterpret_cast<const float2*>(mu2 + col);
            float2 va = *reinterpret_cast<const float2*>(va2 + col);
            float s0 = ga.x * rsqrtf(va.x + BN_EPS), t0 = be.x - mu.x * s0;
            float s1 = ga.y * rsqrtf(va.y + BN_EPS), t1 = be.y - mu.y * s1;
#pragma unroll
            for (int h = 0; h < 2; h++) {
                int row = m0 + wm * 32 + mi * 16 + (lane >> 2) + h * 8;
                if (row >= N) continue;
                size_t gi = (size_t)row * D + col;
                float2 hv = *reinterpret_cast<const float2*>(g_h + gi);
                float f0 = acc[mi][ni][h * 2 + 0] + bb.x;
                float f1 = acc[mi][ni][h * 2 + 1] + bb.y;
                float2 o;
                o.x = (hv.x + f0) * s0 + t0;
                o.y = (hv.y + f1) * s1 + t1;
                *reinterpret_cast<float2*>(out + gi) = o;
            }
        }
    }
}

// ---------------------------------------------------------------------------
extern "C" void kernel_launch(void* const* d_in, const int* in_sizes, int n_in,
                              void* d_out, int out_size) {
    const float* x   = (const float*)d_in[0];
    const int*   ei  = (const int*)d_in[1];
    const float* ea  = (const float*)d_in[2];
    const float* W1  = (const float*)d_in[3];
    const float* b1  = (const float*)d_in[4];
    const float* W2  = (const float*)d_in[5];
    const float* b2  = (const float*)d_in[6];
    const float* g1  = (const float*)d_in[7];
    const float* be1 = (const float*)d_in[8];
    const float* mu1 = (const float*)d_in[9];
    const float* va1 = (const float*)d_in[10];
    const float* g2  = (const float*)d_in[11];
    const float* be2 = (const float*)d_in[12];
    const float* mu2 = (const float*)d_in[13];
    const float* va2 = (const float*)d_in[14];
    float*       out = (float*)d_out;

    int N = in_sizes[0] / D;
    int E = in_sizes[2] / D;

    cudaFuncSetAttribute(gemm1_tc, cudaFuncAttributeMaxDynamicSharedMemorySize, SM_BYTES);
    cudaFuncSetAttribute(gemm2_tc, cudaFuncAttributeMaxDynamicSharedMemorySize, SM_BYTES);

    // CSR build (int atomics only)
    zero_cnt_kernel<<<(N + 255) / 256, 256>>>(N);
    count_kernel<<<(E + 255) / 256, 256>>>(ei, E);
    scan_kernel<<<1, 1024>>>(N);
    fill_kernel<<<(E + 255) / 256, 256>>>(ei, E);

    // gather + bn1 + split (replaces zero/scatter/prep_a)
    gather_kernel<<<(N * 64 + 255) / 256, 256>>>(x, ei, ea, g1, be1, mu1, va1, N, E);

    split_w_kernel<<<(2 * (D * D / 4) + 255) / 256, 256>>>(W1, W2);

    dim3 grid((N + 127) / 128, 2);
    gemm1_tc<<<grid, 256, SM_BYTES>>>(b1, N);
    gemm2_tc<<<grid, 256, SM_BYTES>>>(b2, g2, be2, mu2, va2, out, N);
}

// round 8
// speedup vs baseline: 1.5956x; 1.0136x over previous
#include <cuda_runtime.h>
#include <cuda_bf16.h>
#include <math.h>
#include <stdint.h>

#define D       256
#define D4      64
#define NMAX    50000
#define EMAX    301000
#define BN_EPS  1e-5f
#define KCH     32
#define NCHUNK  8
#define STRIDE  40            // padded smem row stride in bf16 (80B) for k=32

// persistent scratch (no allocs allowed)
__device__ int            g_cnt[NMAX], g_off[NMAX], g_cur[NMAX];
__device__ int            g_idx[EMAX];
__device__ float          g_h  [(size_t)NMAX * D];
__device__ __nv_bfloat16  g_a_hi[(size_t)NMAX * D];
__device__ __nv_bfloat16  g_a_lo[(size_t)NMAX * D];
__device__ __nv_bfloat16  g_m_hi[(size_t)NMAX * D];
__device__ __nv_bfloat16  g_m_lo[(size_t)NMAX * D];
__device__ __nv_bfloat16  g_w1_hi[D * D], g_w1_lo[D * D];
__device__ __nv_bfloat16  g_w2_hi[D * D], g_w2_lo[D * D];

// ---------------- helpers ----------------------------------------------------
__device__ __forceinline__ uint32_t smem_u32(const void* p) {
    uint32_t a;
    asm("{ .reg .u64 t; cvta.to.shared.u64 t, %1; cvt.u32.u64 %0, t; }" : "=r"(a) : "l"(p));
    return a;
}
__device__ __forceinline__ void ldsm_x4(uint32_t* r, uint32_t addr) {
    asm volatile("ldmatrix.sync.aligned.m8n8.x4.shared.b16 {%0,%1,%2,%3}, [%4];"
        : "=r"(r[0]), "=r"(r[1]), "=r"(r[2]), "=r"(r[3]) : "r"(addr));
}
__device__ __forceinline__ void mma_bf16(float* c, const uint32_t* a, const uint32_t* b) {
    asm volatile("mma.sync.aligned.m16n8k16.row.col.f32.bf16.bf16.f32 "
        "{%0,%1,%2,%3}, {%4,%5,%6,%7}, {%8,%9}, {%0,%1,%2,%3};"
        : "+f"(c[0]), "+f"(c[1]), "+f"(c[2]), "+f"(c[3])
        : "r"(a[0]), "r"(a[1]), "r"(a[2]), "r"(a[3]), "r"(b[0]), "r"(b[1]));
}
__device__ __forceinline__ void split_bf16(float v, __nv_bfloat16& h, __nv_bfloat16& l) {
    h = __float2bfloat16(v);
    l = __float2bfloat16(v - __bfloat162float(h));
}
__device__ __forceinline__ void cp16(uint32_t saddr, const void* gaddr) {
    asm volatile("cp.async.cg.shared.global [%0], [%1], 16;" :: "r"(saddr), "l"(gaddr));
}
#define CP_COMMIT() asm volatile("cp.async.commit_group;" ::: "memory")
#define CP_WAIT(n)  asm volatile("cp.async.wait_group %0;" :: "n"(n) : "memory")

// per-buffer smem layout (bytes): four 128 x 32 bf16 tiles, stride 40
#define T_AHI  0
#define T_ALO  10240
#define T_BHI  20480
#define T_BLO  30720
#define BUF_BYTES 40960
#define SM_BYTES  (2 * BUF_BYTES)      // 80 KB -> 2 CTAs/SM

// ====================== CSR build (no float atomics) ========================
__global__ void count_kernel(const int* __restrict__ ei, int E) {
    int i = blockIdx.x * blockDim.x + threadIdx.x;
    if (i < E) atomicAdd(&g_cnt[ei[E + i]], 1);
}
// single-block exclusive scan over N counts -> g_off, g_cur
__global__ void scan_kernel(int N) {
    __shared__ int part[1024];
    int tid = threadIdx.x;
    int per = (N + 1023) >> 10;
    int lo = tid * per;
    int hi = lo + per; if (hi > N) hi = N;
    int s = 0;
    for (int i = lo; i < hi; i++) s += g_cnt[i];
    part[tid] = s;
    __syncthreads();
    for (int o = 1; o < 1024; o <<= 1) {
        int v = (tid >= o) ? part[tid - o] : 0;
        __syncthreads();
        part[tid] += v;
        __syncthreads();
    }
    int run = (tid == 0) ? 0 : part[tid - 1];
    for (int i = lo; i < hi; i++) {
        g_off[i] = run;
        g_cur[i] = run;
        run += g_cnt[i];
    }
}
__global__ void fill_kernel(const int* __restrict__ ei, int E) {
    int i = blockIdx.x * blockDim.x + threadIdx.x;
    if (i < E) {
        int d = ei[E + i];
        int p = atomicAdd(&g_cur[d], 1);
        g_idx[p] = i;
    }
}

// gather: agg = sum relu(x[src]+ea); h = 2x+agg -> g_h; bn1(h) split -> g_a
// unrolled x2 for MLP on the 3-deep idx->ei->x chains
__global__ void gather_kernel(const float* __restrict__ x,
                              const int* __restrict__ ei,
                              const float* __restrict__ ea,
                              const float* __restrict__ g1, const float* __restrict__ be1,
                              const float* __restrict__ mu1, const float* __restrict__ va1,
                              int N, int E) {
    int t = blockIdx.x * blockDim.x + threadIdx.x;
    int node = t >> 6, c = t & 63;
    if (node >= N) return;
    int off = g_off[node], deg = g_cnt[node];

    float4 sum = make_float4(0.f, 0.f, 0.f, 0.f);
    int j = 0;
    for (; j + 2 <= deg; j += 2) {
        int e0 = g_idx[off + j];
        int e1 = g_idx[off + j + 1];
        int s0 = ei[e0], s1 = ei[e1];
        float4 x0 = reinterpret_cast<const float4*>(x)[(size_t)s0 * D4 + c];
        float4 a0 = reinterpret_cast<const float4*>(ea)[(size_t)e0 * D4 + c];
        float4 x1 = reinterpret_cast<const float4*>(x)[(size_t)s1 * D4 + c];
        float4 a1 = reinterpret_cast<const float4*>(ea)[(size_t)e1 * D4 + c];
        sum.x += fmaxf(x0.x + a0.x, 0.f) + fmaxf(x1.x + a1.x, 0.f);
        sum.y += fmaxf(x0.y + a0.y, 0.f) + fmaxf(x1.y + a1.y, 0.f);
        sum.z += fmaxf(x0.z + a0.z, 0.f) + fmaxf(x1.z + a1.z, 0.f);
        sum.w += fmaxf(x0.w + a0.w, 0.f) + fmaxf(x1.w + a1.w, 0.f);
    }
    if (j < deg) {
        int e0 = g_idx[off + j];
        int s0 = ei[e0];
        float4 x0 = reinterpret_cast<const float4*>(x)[(size_t)s0 * D4 + c];
        float4 a0 = reinterpret_cast<const float4*>(ea)[(size_t)e0 * D4 + c];
        sum.x += fmaxf(x0.x + a0.x, 0.f);
        sum.y += fmaxf(x0.y + a0.y, 0.f);
        sum.z += fmaxf(x0.z + a0.z, 0.f);
        sum.w += fmaxf(x0.w + a0.w, 0.f);
    }
    float4 xn = reinterpret_cast<const float4*>(x)[(size_t)node * D4 + c];
    float4 h;
    h.x = 2.f * xn.x + sum.x; h.y = 2.f * xn.y + sum.y;
    h.z = 2.f * xn.z + sum.z; h.w = 2.f * xn.w + sum.w;
    reinterpret_cast<float4*>(g_h)[(size_t)node * D4 + c] = h;

    float4 ga = reinterpret_cast<const float4*>(g1)[c];
    float4 va = reinterpret_cast<const float4*>(va1)[c];
    float4 be = reinterpret_cast<const float4*>(be1)[c];
    float4 mu = reinterpret_cast<const float4*>(mu1)[c];
    float v[4];
    float sc;
    sc = ga.x * rsqrtf(va.x + BN_EPS); v[0] = h.x * sc + (be.x - mu.x * sc);
    sc = ga.y * rsqrtf(va.y + BN_EPS); v[1] = h.y * sc + (be.y - mu.y * sc);
    sc = ga.z * rsqrtf(va.z + BN_EPS); v[2] = h.z * sc + (be.z - mu.z * sc);
    sc = ga.w * rsqrtf(va.w + BN_EPS); v[3] = h.w * sc + (be.w - mu.w * sc);
    union { uint2 u; __nv_bfloat16 b[4]; } ph, pl;
#pragma unroll
    for (int q = 0; q < 4; q++) split_bf16(v[q], ph.b[q], pl.b[q]);
    reinterpret_cast<uint2*>(g_a_hi)[(size_t)node * D4 + c] = ph.u;
    reinterpret_cast<uint2*>(g_a_lo)[(size_t)node * D4 + c] = pl.u;
}

// split both weight matrices into bf16 hi/lo (once per launch, cheap)
__global__ void split_w_kernel(const float* __restrict__ W1,
                               const float* __restrict__ W2) {
    int i = blockIdx.x * blockDim.x + threadIdx.x;
    if (i >= 2 * (D * D / 4)) return;
    bool second = i >= (D * D / 4);
    int j = second ? i - D * D / 4 : i;
    float4 w = reinterpret_cast<const float4*>(second ? W2 : W1)[j];
    __nv_bfloat16* hi = second ? g_w2_hi : g_w1_hi;
    __nv_bfloat16* lo = second ? g_w2_lo : g_w1_lo;
    float v[4] = {w.x, w.y, w.z, w.w};
    union { uint2 u; __nv_bfloat16 b[4]; } ph, pl;
#pragma unroll
    for (int t = 0; t < 4; t++) split_bf16(v[t], ph.b[t], pl.b[t]);
    reinterpret_cast<uint2*>(hi)[j] = ph.u;
    reinterpret_cast<uint2*>(lo)[j] = pl.u;
}

// ====================== GEMM machinery (k=32 chunks) ========================
__device__ __forceinline__ void stage_chunk(uint32_t sbase,
                                            const __nv_bfloat16* __restrict__ Ahi,
                                            const __nv_bfloat16* __restrict__ Alo,
                                            const __nv_bfloat16* __restrict__ Whi,
                                            const __nv_bfloat16* __restrict__ Wlo,
                                            int m0, int n0, int ch, int N, int tid) {
    int r  = tid >> 1;
    int kh = (tid & 1) * 16;                       // elements (32B half-row)
    int arow = m0 + r; if (arow >= N) arow = 0;    // clamp: garbage rows unused
    size_t  agi = (size_t)arow * D + ch * KCH + kh;
    size_t  bgi = (size_t)(n0 + r) * D + ch * KCH + kh;
    uint32_t soff = (uint32_t)(r * STRIDE + kh) * 2;
#pragma unroll
    for (int q = 0; q < 2; q++) {
        cp16(sbase + T_AHI + soff + q * 16, Ahi + agi + q * 8);
        cp16(sbase + T_ALO + soff + q * 16, Alo + agi + q * 8);
        cp16(sbase + T_BHI + soff + q * 16, Whi + bgi + q * 8);
        cp16(sbase + T_BLO + soff + q * 16, Wlo + bgi + q * 8);
    }
}

__device__ __forceinline__ void mma_chunk(uint32_t base, int lane, int wm, int wn,
                                          float acc[2][8][4]) {
#pragma unroll
    for (int ks = 0; ks < 2; ks++) {
        uint32_t ah[2][4], al[2][4];
#pragma unroll
        for (int mi = 0; mi < 2; mi++) {
            int row = wm * 32 + mi * 16 + (lane & 15);
            int kk  = ks * 16 + ((lane >> 4) << 3);
            uint32_t ad = base + T_AHI + (uint32_t)(row * STRIDE + kk) * 2;
            ldsm_x4(ah[mi], ad);
            ldsm_x4(al[mi], ad + (T_ALO - T_AHI));
        }
#pragma unroll
        for (int nb = 0; nb < 4; nb++) {
            uint32_t bh[4], bl[4];
            int nrow = wn * 64 + nb * 16 + (lane & 7) + ((lane >> 4) << 3);
            int kk   = ks * 16 + (((lane >> 3) & 1) << 3);
            uint32_t bd = base + T_BHI + (uint32_t)(nrow * STRIDE + kk) * 2;
            ldsm_x4(bh, bd);
            ldsm_x4(bl, bd + (T_BLO - T_BHI));
#pragma unroll
            for (int mi = 0; mi < 2; mi++) {
#pragma unroll
                for (int hf = 0; hf < 2; hf++) {
                    float* c = acc[mi][nb * 2 + hf];
                    mma_bf16(c, ah[mi], &bh[hf * 2]);
                    mma_bf16(c, ah[mi], &bl[hf * 2]);
                    mma_bf16(c, al[mi], &bh[hf * 2]);
                }
            }
        }
    }
}

__device__ __forceinline__ void gemm_mainloop(uint32_t smb,
                                              const __nv_bfloat16* Ahi, const __nv_bfloat16* Alo,
                                              const __nv_bfloat16* Whi, const __nv_bfloat16* Wlo,
                                              int m0, int n0, int N, int tid,
                                              int lane, int wm, int wn,
                                              float acc[2][8][4]) {
    stage_chunk(smb, Ahi, Alo, Whi, Wlo, m0, n0, 0, N, tid);
    CP_COMMIT();
#pragma unroll
    for (int ch = 0; ch < NCHUNK; ch++) {
        if (ch < NCHUNK - 1) {
            stage_chunk(smb + ((ch + 1) & 1) * BUF_BYTES, Ahi, Alo, Whi, Wlo,
                        m0, n0, ch + 1, N, tid);
            CP_COMMIT();
            CP_WAIT(1);
        } else {
            CP_WAIT(0);
        }
        __syncthreads();
        mma_chunk(smb + (ch & 1) * BUF_BYTES, lane, wm, wn, acc);
        __syncthreads();
    }
}

// ------------- GEMM1: mid = gelu(a @ W1^T + b1), split to bf16 --------------
// grid = (2 n-tiles, m-tiles): consecutive bids share the m-block -> L2 reuse of A
__global__ void __launch_bounds__(256, 2)
gemm1_tc(const float* __restrict__ b1, int N) {
    extern __shared__ char sm[];
    uint32_t smb = smem_u32(sm);
    const int tid = threadIdx.x, lane = tid & 31, wid = tid >> 5;
    const int wm = wid & 3, wn = wid >> 2;
    const int m0 = blockIdx.y * 128;
    const int n0 = blockIdx.x * 128;

    float acc[2][8][4];
#pragma unroll
    for (int a = 0; a < 2; a++)
#pragma unroll
        for (int b = 0; b < 8; b++)
#pragma unroll
            for (int c = 0; c < 4; c++) acc[a][b][c] = 0.f;

    gemm_mainloop(smb, g_a_hi, g_a_lo, g_w1_hi, g_w1_lo, m0, n0, N, tid, lane, wm, wn, acc);

#pragma unroll
    for (int mi = 0; mi < 2; mi++) {
#pragma unroll
        for (int ni = 0; ni < 8; ni++) {
            int col = n0 + wn * 64 + ni * 8 + (lane & 3) * 2;
            float2 bb = *reinterpret_cast<const float2*>(b1 + col);
#pragma unroll
            for (int h = 0; h < 2; h++) {
                int row = m0 + wm * 32 + mi * 16 + (lane >> 2) + h * 8;
                if (row >= N) continue;
                float u0 = acc[mi][ni][h * 2 + 0] + bb.x;
                float u1 = acc[mi][ni][h * 2 + 1] + bb.y;
                float gl0 = 0.5f * u0 * (1.f + erff(u0 * 0.70710678118f));
                float gl1 = 0.5f * u1 * (1.f + erff(u1 * 0.70710678118f));
                union { uint32_t u; __nv_bfloat16 b[2]; } ph, pl;
                split_bf16(gl0, ph.b[0], pl.b[0]);
                split_bf16(gl1, ph.b[1], pl.b[1]);
                *reinterpret_cast<uint32_t*>(g_m_hi + (size_t)row * D + col) = ph.u;
                *reinterpret_cast<uint32_t*>(g_m_lo + (size_t)row * D + col) = pl.u;
            }
        }
    }
}

// ------------- GEMM2: out = bn2(h + mid @ W2^T + b2) -------------------------
__global__ void __launch_bounds__(256, 2)
gemm2_tc(const float* __restrict__ b2,
         const float* __restrict__ g2, const float* __restrict__ be2,
         const float* __restrict__ mu2, const float* __restrict__ va2,
         float* __restrict__ out, int N) {
    extern __shared__ char sm[];
    uint32_t smb = smem_u32(sm);
    const int tid = threadIdx.x, lane = tid & 31, wid = tid >> 5;
    const int wm = wid & 3, wn = wid >> 2;
    const int m0 = blockIdx.y * 128;
    const int n0 = blockIdx.x * 128;

    float acc[2][8][4];
#pragma unroll
    for (int a = 0; a < 2; a++)
#pragma unroll
        for (int b = 0; b < 8; b++)
#pragma unroll
            for (int c = 0; c < 4; c++) acc[a][b][c] = 0.f;

    gemm_mainloop(smb, g_m_hi, g_m_lo, g_w2_hi, g_w2_lo, m0, n0, N, tid, lane, wm, wn, acc);

#pragma unroll
    for (int mi = 0; mi < 2; mi++) {
#pragma unroll
        for (int ni = 0; ni < 8; ni++) {
            int col = n0 + wn * 64 + ni * 8 + (lane & 3) * 2;
            float2 bb = *reinterpret_cast<const float2*>(b2 + col);
            float2 ga = *reinterpret_cast<const float2*>(g2 + col);
            float2 be = *reinterpret_cast<const float2*>(be2 + col);
            float2 mu = *reinterpret_cast<const float2*>(mu2 + col);
            float2 va = *reinterpret_cast<const float2*>(va2 + col);
            float s0 = ga.x * rsqrtf(va.x + BN_EPS), t0 = be.x - mu.x * s0;
            float s1 = ga.y * rsqrtf(va.y + BN_EPS), t1 = be.y - mu.y * s1;
#pragma unroll
            for (int h = 0; h < 2; h++) {
                int row = m0 + wm * 32 + mi * 16 + (lane >> 2) + h * 8;
                if (row >= N) continue;
                size_t gi = (size_t)row * D + col;
                float2 hv = *reinterpret_cast<const float2*>(g_h + gi);
                float f0 = acc[mi][ni][h * 2 + 0] + bb.x;
                float f1 = acc[mi][ni][h * 2 + 1] + bb.y;
                float2 o;
                o.x = (hv.x + f0) * s0 + t0;
                o.y = (hv.y + f1) * s1 + t1;
                *reinterpret_cast<float2*>(out + gi) = o;
            }
        }
    }
}

// ---------------------------------------------------------------------------
extern "C" void kernel_launch(void* const* d_in, const int* in_sizes, int n_in,
                              void* d_out, int out_size) {
    const float* x   = (const float*)d_in[0];
    const int*   ei  = (const int*)d_in[1];
    const float* ea  = (const float*)d_in[2];
    const float* W1  = (const float*)d_in[3];
    const float* b1  = (const float*)d_in[4];
    const float* W2  = (const float*)d_in[5];
    const float* b2  = (const float*)d_in[6];
    const float* g1  = (const float*)d_in[7];
    const float* be1 = (const float*)d_in[8];
    const float* mu1 = (const float*)d_in[9];
    const float* va1 = (const float*)d_in[10];
    const float* g2  = (const float*)d_in[11];
    const float* be2 = (const float*)d_in[12];
    const float* mu2 = (const float*)d_in[13];
    const float* va2 = (const float*)d_in[14];
    float*       out = (float*)d_out;

    int N = in_sizes[0] / D;
    int E = in_sizes[2] / D;

    cudaFuncSetAttribute(gemm1_tc, cudaFuncAttributeMaxDynamicSharedMemorySize, SM_BYTES);
    cudaFuncSetAttribute(gemm2_tc, cudaFuncAttributeMaxDynamicSharedMemorySize, SM_BYTES);

    // zero degree counts via memset (capturable; removes one kernel launch)
    void* cnt_ptr = nullptr;
    cudaGetSymbolAddress(&cnt_ptr, g_cnt);
    cudaMemsetAsync(cnt_ptr, 0, (size_t)N * sizeof(int));

    // CSR build (int atomics only)
    count_kernel<<<(E + 255) / 256, 256>>>(ei, E);
    scan_kernel<<<1, 1024>>>(N);
    fill_kernel<<<(E + 255) / 256, 256>>>(ei, E);

    // gather + bn1 + split (no float atomics)
    gather_kernel<<<(N * 64 + 255) / 256, 256>>>(x, ei, ea, g1, be1, mu1, va1, N, E);

    split_w_kernel<<<(2 * (D * D / 4) + 255) / 256, 256>>>(W1, W2);

    dim3 grid(2, (N + 127) / 128);
    gemm1_tc<<<grid, 256, SM_BYTES>>>(b1, N);
    gemm2_tc<<<grid, 256, SM_BYTES>>>(b2, g2, be2, mu2, va2, out, N);
}

// round 9
// speedup vs baseline: 1.6718x; 1.0477x over previous
#include <cuda_runtime.h>
#include <cuda_bf16.h>
#include <math.h>
#include <stdint.h>

#define D       256
#define D4      64
#define NMAX    50000
#define EMAX    301000
#define BN_EPS  1e-5f
#define KCH     32
#define NCHUNK  8
#define STRIDE  40            // padded smem row stride in bf16 (80B) for k=32

// persistent scratch (no allocs allowed)
__device__ int            g_cnt[NMAX], g_off[NMAX], g_cur[NMAX];
__device__ int            g_idx[EMAX];
__device__ float          g_h  [(size_t)NMAX * D];
__device__ __nv_bfloat16  g_a_hi[(size_t)NMAX * D];
__device__ __nv_bfloat16  g_a_lo[(size_t)NMAX * D];
__device__ __nv_bfloat16  g_m_hi[(size_t)NMAX * D];
__device__ __nv_bfloat16  g_m_lo[(size_t)NMAX * D];
__device__ __nv_bfloat16  g_w1_hi[D * D], g_w1_lo[D * D];
__device__ __nv_bfloat16  g_w2_hi[D * D], g_w2_lo[D * D];

// ---------------- helpers ----------------------------------------------------
__device__ __forceinline__ uint32_t smem_u32(const void* p) {
    uint32_t a;
    asm("{ .reg .u64 t; cvta.to.shared.u64 t, %1; cvt.u32.u64 %0, t; }" : "=r"(a) : "l"(p));
    return a;
}
__device__ __forceinline__ void ldsm_x4(uint32_t* r, uint32_t addr) {
    asm volatile("ldmatrix.sync.aligned.m8n8.x4.shared.b16 {%0,%1,%2,%3}, [%4];"
        : "=r"(r[0]), "=r"(r[1]), "=r"(r[2]), "=r"(r[3]) : "r"(addr));
}
__device__ __forceinline__ void mma_bf16(float* c, const uint32_t* a, const uint32_t* b) {
    asm volatile("mma.sync.aligned.m16n8k16.row.col.f32.bf16.bf16.f32 "
        "{%0,%1,%2,%3}, {%4,%5,%6,%7}, {%8,%9}, {%0,%1,%2,%3};"
        : "+f"(c[0]), "+f"(c[1]), "+f"(c[2]), "+f"(c[3])
        : "r"(a[0]), "r"(a[1]), "r"(a[2]), "r"(a[3]), "r"(b[0]), "r"(b[1]));
}
__device__ __forceinline__ void split_bf16(float v, __nv_bfloat16& h, __nv_bfloat16& l) {
    h = __float2bfloat16(v);
    l = __float2bfloat16(v - __bfloat162float(h));
}
__device__ __forceinline__ void cp16(uint32_t saddr, const void* gaddr) {
    asm volatile("cp.async.cg.shared.global [%0], [%1], 16;" :: "r"(saddr), "l"(gaddr));
}
#define CP_COMMIT() asm volatile("cp.async.commit_group;" ::: "memory")
#define CP_WAIT(n)  asm volatile("cp.async.wait_group %0;" :: "n"(n) : "memory")

// per-buffer smem layout (bytes): four 128 x 32 bf16 tiles, stride 40
#define T_AHI  0
#define T_ALO  10240
#define T_BHI  20480
#define T_BLO  30720
#define BUF_BYTES 40960
#define SM_BYTES  (2 * BUF_BYTES)      // 80 KB -> 2 CTAs/SM

// ====================== CSR build (no float atomics) ========================
__global__ void count_kernel(const int* __restrict__ ei, int E) {
    int i = blockIdx.x * blockDim.x + threadIdx.x;
    if (i < E) atomicAdd(&g_cnt[ei[E + i]], 1);
}
__global__ void scan_kernel(int N) {
    __shared__ int part[1024];
    int tid = threadIdx.x;
    int per = (N + 1023) >> 10;
    int lo = tid * per;
    int hi = lo + per; if (hi > N) hi = N;
    int s = 0;
    for (int i = lo; i < hi; i++) s += g_cnt[i];
    part[tid] = s;
    __syncthreads();
    for (int o = 1; o < 1024; o <<= 1) {
        int v = (tid >= o) ? part[tid - o] : 0;
        __syncthreads();
        part[tid] += v;
        __syncthreads();
    }
    int run = (tid == 0) ? 0 : part[tid - 1];
    for (int i = lo; i < hi; i++) {
        g_off[i] = run;
        g_cur[i] = run;
        run += g_cnt[i];
    }
}
__global__ void fill_kernel(const int* __restrict__ ei, int E) {
    int i = blockIdx.x * blockDim.x + threadIdx.x;
    if (i < E) {
        int d = ei[E + i];
        int p = atomicAdd(&g_cur[d], 1);
        g_idx[p] = i;
    }
}

// gather: agg = sum relu(x[src]+ea); h = 2x+agg -> g_h; bn1(h) split -> g_a
__global__ void gather_kernel(const float* __restrict__ x,
                              const int* __restrict__ ei,
                              const float* __restrict__ ea,
                              const float* __restrict__ g1, const float* __restrict__ be1,
                              const float* __restrict__ mu1, const float* __restrict__ va1,
                              int N, int E) {
    int t = blockIdx.x * blockDim.x + threadIdx.x;
    int node = t >> 6, c = t & 63;
    if (node >= N) return;
    int off = g_off[node], deg = g_cnt[node];

    float4 sum = make_float4(0.f, 0.f, 0.f, 0.f);
    int j = 0;
    for (; j + 2 <= deg; j += 2) {
        int e0 = g_idx[off + j];
        int e1 = g_idx[off + j + 1];
        int s0 = ei[e0], s1 = ei[e1];
        float4 x0 = reinterpret_cast<const float4*>(x)[(size_t)s0 * D4 + c];
        float4 a0 = reinterpret_cast<const float4*>(ea)[(size_t)e0 * D4 + c];
        float4 x1 = reinterpret_cast<const float4*>(x)[(size_t)s1 * D4 + c];
        float4 a1 = reinterpret_cast<const float4*>(ea)[(size_t)e1 * D4 + c];
        sum.x += fmaxf(x0.x + a0.x, 0.f) + fmaxf(x1.x + a1.x, 0.f);
        sum.y += fmaxf(x0.y + a0.y, 0.f) + fmaxf(x1.y + a1.y, 0.f);
        sum.z += fmaxf(x0.z + a0.z, 0.f) + fmaxf(x1.z + a1.z, 0.f);
        sum.w += fmaxf(x0.w + a0.w, 0.f) + fmaxf(x1.w + a1.w, 0.f);
    }
    if (j < deg) {
        int e0 = g_idx[off + j];
        int s0 = ei[e0];
        float4 x0 = reinterpret_cast<const float4*>(x)[(size_t)s0 * D4 + c];
        float4 a0 = reinterpret_cast<const float4*>(ea)[(size_t)e0 * D4 + c];
        sum.x += fmaxf(x0.x + a0.x, 0.f);
        sum.y += fmaxf(x0.y + a0.y, 0.f);
        sum.z += fmaxf(x0.z + a0.z, 0.f);
        sum.w += fmaxf(x0.w + a0.w, 0.f);
    }
    float4 xn = reinterpret_cast<const float4*>(x)[(size_t)node * D4 + c];
    float4 h;
    h.x = 2.f * xn.x + sum.x; h.y = 2.f * xn.y + sum.y;
    h.z = 2.f * xn.z + sum.z; h.w = 2.f * xn.w + sum.w;
    reinterpret_cast<float4*>(g_h)[(size_t)node * D4 + c] = h;

    float4 ga = reinterpret_cast<const float4*>(g1)[c];
    float4 va = reinterpret_cast<const float4*>(va1)[c];
    float4 be = reinterpret_cast<const float4*>(be1)[c];
    float4 mu = reinterpret_cast<const float4*>(mu1)[c];
    float v[4];
    float sc;
    sc = ga.x * rsqrtf(va.x + BN_EPS); v[0] = h.x * sc + (be.x - mu.x * sc);
    sc = ga.y * rsqrtf(va.y + BN_EPS); v[1] = h.y * sc + (be.y - mu.y * sc);
    sc = ga.z * rsqrtf(va.z + BN_EPS); v[2] = h.z * sc + (be.z - mu.z * sc);
    sc = ga.w * rsqrtf(va.w + BN_EPS); v[3] = h.w * sc + (be.w - mu.w * sc);
    union { uint2 u; __nv_bfloat16 b[4]; } ph, pl;
#pragma unroll
    for (int q = 0; q < 4; q++) split_bf16(v[q], ph.b[q], pl.b[q]);
    reinterpret_cast<uint2*>(g_a_hi)[(size_t)node * D4 + c] = ph.u;
    reinterpret_cast<uint2*>(g_a_lo)[(size_t)node * D4 + c] = pl.u;
}

// split both weight matrices into bf16 hi/lo (once per launch, cheap)
__global__ void split_w_kernel(const float* __restrict__ W1,
                               const float* __restrict__ W2) {
    int i = blockIdx.x * blockDim.x + threadIdx.x;
    if (i >= 2 * (D * D / 4)) return;
    bool second = i >= (D * D / 4);
    int j = second ? i - D * D / 4 : i;
    float4 w = reinterpret_cast<const float4*>(second ? W2 : W1)[j];
    __nv_bfloat16* hi = second ? g_w2_hi : g_w1_hi;
    __nv_bfloat16* lo = second ? g_w2_lo : g_w1_lo;
    float v[4] = {w.x, w.y, w.z, w.w};
    union { uint2 u; __nv_bfloat16 b[4]; } ph, pl;
#pragma unroll
    for (int t = 0; t < 4; t++) split_bf16(v[t], ph.b[t], pl.b[t]);
    reinterpret_cast<uint2*>(hi)[j] = ph.u;
    reinterpret_cast<uint2*>(lo)[j] = pl.u;
}

// ====================== GEMM machinery (512 thr, 16 warps) ==================
// stage: 512 threads, each thread one cp16 per tile (128 rows x 32 k)
__device__ __forceinline__ void stage_chunk(uint32_t sbase,
                                            const __nv_bfloat16* __restrict__ Ahi,
                                            const __nv_bfloat16* __restrict__ Alo,
                                            const __nv_bfloat16* __restrict__ Whi,
                                            const __nv_bfloat16* __restrict__ Wlo,
                                            int m0, int n0, int ch, int N, int tid) {
    int r  = tid >> 2;
    int kq = (tid & 3) * 8;                        // 8 bf16 = 16B
    int arow = m0 + r; if (arow >= N) arow = 0;    // clamp: garbage rows unused
    size_t  agi = (size_t)arow * D + ch * KCH + kq;
    size_t  bgi = (size_t)(n0 + r) * D + ch * KCH + kq;
    uint32_t soff = (uint32_t)(r * STRIDE + kq) * 2;
    cp16(sbase + T_AHI + soff, Ahi + agi);
    cp16(sbase + T_ALO + soff, Alo + agi);
    cp16(sbase + T_BHI + soff, Whi + bgi);
    cp16(sbase + T_BLO + soff, Wlo + bgi);
}

// warp tile 16m x 64n; acc[8][4]
__device__ __forceinline__ void mma_chunk(uint32_t base, int lane, int wm, int wn,
                                          float acc[8][4]) {
#pragma unroll
    for (int ks = 0; ks < 2; ks++) {
        uint32_t ah[4], al[4];
        {
            int row = wm * 16 + (lane & 15);
            int kk  = ks * 16 + ((lane >> 4) << 3);
            uint32_t ad = base + T_AHI + (uint32_t)(row * STRIDE + kk) * 2;
            ldsm_x4(ah, ad);
            ldsm_x4(al, ad + (T_ALO - T_AHI));
        }
#pragma unroll
        for (int nb = 0; nb < 4; nb++) {
            uint32_t bh[4], bl[4];
            int nrow = wn * 64 + nb * 16 + (lane & 7) + ((lane >> 4) << 3);
            int kk   = ks * 16 + (((lane >> 3) & 1) << 3);
            uint32_t bd = base + T_BHI + (uint32_t)(nrow * STRIDE + kk) * 2;
            ldsm_x4(bh, bd);
            ldsm_x4(bl, bd + (T_BLO - T_BHI));
#pragma unroll
            for (int hf = 0; hf < 2; hf++) {
                float* c = acc[nb * 2 + hf];
                mma_bf16(c, ah, &bh[hf * 2]);
                mma_bf16(c, ah, &bl[hf * 2]);
                mma_bf16(c, al, &bh[hf * 2]);
            }
        }
    }
}

__device__ __forceinline__ void gemm_mainloop(uint32_t smb,
                                              const __nv_bfloat16* Ahi, const __nv_bfloat16* Alo,
                                              const __nv_bfloat16* Whi, const __nv_bfloat16* Wlo,
                                              int m0, int n0, int N, int tid,
                                              int lane, int wm, int wn,
                                              float acc[8][4]) {
    stage_chunk(smb, Ahi, Alo, Whi, Wlo, m0, n0, 0, N, tid);
    CP_COMMIT();
#pragma unroll
    for (int ch = 0; ch < NCHUNK; ch++) {
        if (ch < NCHUNK - 1) {
            stage_chunk(smb + ((ch + 1) & 1) * BUF_BYTES, Ahi, Alo, Whi, Wlo,
                        m0, n0, ch + 1, N, tid);
            CP_COMMIT();
            CP_WAIT(1);
        } else {
            CP_WAIT(0);
        }
        __syncthreads();
        mma_chunk(smb + (ch & 1) * BUF_BYTES, lane, wm, wn, acc);
        __syncthreads();
    }
}

// ------------- GEMM1: mid = gelu(a @ W1^T + b1), split to bf16 --------------
__global__ void __launch_bounds__(512, 2)
gemm1_tc(const float* __restrict__ b1, int N) {
    extern __shared__ char sm[];
    uint32_t smb = smem_u32(sm);
    const int tid = threadIdx.x, lane = tid & 31, wid = tid >> 5;
    const int wm = wid & 7, wn = wid >> 3;
    const int m0 = blockIdx.y * 128;
    const int n0 = blockIdx.x * 128;

    float acc[8][4];
#pragma unroll
    for (int b = 0; b < 8; b++)
#pragma unroll
        for (int c = 0; c < 4; c++) acc[b][c] = 0.f;

    gemm_mainloop(smb, g_a_hi, g_a_lo, g_w1_hi, g_w1_lo, m0, n0, N, tid, lane, wm, wn, acc);

#pragma unroll
    for (int ni = 0; ni < 8; ni++) {
        int col = n0 + wn * 64 + ni * 8 + (lane & 3) * 2;
        float2 bb = *reinterpret_cast<const float2*>(b1 + col);
#pragma unroll
        for (int h = 0; h < 2; h++) {
            int row = m0 + wm * 16 + (lane >> 2) + h * 8;
            if (row >= N) continue;
            float u0 = acc[ni][h * 2 + 0] + bb.x;
            float u1 = acc[ni][h * 2 + 1] + bb.y;
            float gl0 = 0.5f * u0 * (1.f + erff(u0 * 0.70710678118f));
            float gl1 = 0.5f * u1 * (1.f + erff(u1 * 0.70710678118f));
            union { uint32_t u; __nv_bfloat16 b[2]; } ph, pl;
            split_bf16(gl0, ph.b[0], pl.b[0]);
            split_bf16(gl1, ph.b[1], pl.b[1]);
            *reinterpret_cast<uint32_t*>(g_m_hi + (size_t)row * D + col) = ph.u;
            *reinterpret_cast<uint32_t*>(g_m_lo + (size_t)row * D + col) = pl.u;
        }
    }
}

// ------------- GEMM2: out = bn2(h + mid @ W2^T + b2) -------------------------
__global__ void __launch_bounds__(512, 2)
gemm2_tc(const float* __restrict__ b2,
         const float* __restrict__ g2, const float* __restrict__ be2,
         const float* __restrict__ mu2, const float* __restrict__ va2,
         float* __restrict__ out, int N) {
    extern __shared__ char sm[];
    uint32_t smb = smem_u32(sm);
    const int tid = threadIdx.x, lane = tid & 31, wid = tid >> 5;
    const int wm = wid & 7, wn = wid >> 3;
    const int m0 = blockIdx.y * 128;
    const int n0 = blockIdx.x * 128;

    float acc[8][4];
#pragma unroll
    for (int b = 0; b < 8; b++)
#pragma unroll
        for (int c = 0; c < 4; c++) acc[b][c] = 0.f;

    gemm_mainloop(smb, g_m_hi, g_m_lo, g_w2_hi, g_w2_lo, m0, n0, N, tid, lane, wm, wn, acc);

#pragma unroll
    for (int ni = 0; ni < 8; ni++) {
        int col = n0 + wn * 64 + ni * 8 + (lane & 3) * 2;
        float2 bb = *reinterpret_cast<const float2*>(b2 + col);
        float2 ga = *reinterpret_cast<const float2*>(g2 + col);
        float2 be = *reinterpret_cast<const float2*>(be2 + col);
        float2 mu = *reinterpret_cast<const float2*>(mu2 + col);
        float2 va = *reinterpret_cast<const float2*>(va2 + col);
        float s0 = ga.x * rsqrtf(va.x + BN_EPS), t0 = be.x - mu.x * s0;
        float s1 = ga.y * rsqrtf(va.y + BN_EPS), t1 = be.y - mu.y * s1;
#pragma unroll
        for (int h = 0; h < 2; h++) {
            int row = m0 + wm * 16 + (lane >> 2) + h * 8;
            if (row >= N) continue;
            size_t gi = (size_t)row * D + col;
            float2 hv = *reinterpret_cast<const float2*>(g_h + gi);
            float f0 = acc[ni][h * 2 + 0] + bb.x;
            float f1 = acc[ni][h * 2 + 1] + bb.y;
            float2 o;
            o.x = (hv.x + f0) * s0 + t0;
            o.y = (hv.y + f1) * s1 + t1;
            *reinterpret_cast<float2*>(out + gi) = o;
        }
    }
}

// ---------------------------------------------------------------------------
extern "C" void kernel_launch(void* const* d_in, const int* in_sizes, int n_in,
                              void* d_out, int out_size) {
    const float* x   = (const float*)d_in[0];
    const int*   ei  = (const int*)d_in[1];
    const float* ea  = (const float*)d_in[2];
    const float* W1  = (const float*)d_in[3];
    const float* b1  = (const float*)d_in[4];
    const float* W2  = (const float*)d_in[5];
    const float* b2  = (const float*)d_in[6];
    const float* g1  = (const float*)d_in[7];
    const float* be1 = (const float*)d_in[8];
    const float* mu1 = (const float*)d_in[9];
    const float* va1 = (const float*)d_in[10];
    const float* g2  = (const float*)d_in[11];
    const float* be2 = (const float*)d_in[12];
    const float* mu2 = (const float*)d_in[13];
    const float* va2 = (const float*)d_in[14];
    float*       out = (float*)d_out;

    int N = in_sizes[0] / D;
    int E = in_sizes[2] / D;

    cudaFuncSetAttribute(gemm1_tc, cudaFuncAttributeMaxDynamicSharedMemorySize, SM_BYTES);
    cudaFuncSetAttribute(gemm2_tc, cudaFuncAttributeMaxDynamicSharedMemorySize, SM_BYTES);

    void* cnt_ptr = nullptr;
    cudaGetSymbolAddress(&cnt_ptr, g_cnt);
    cudaMemsetAsync(cnt_ptr, 0, (size_t)N * sizeof(int));

    count_kernel<<<(E + 255) / 256, 256>>>(ei, E);
    scan_kernel<<<1, 1024>>>(N);
    fill_kernel<<<(E + 255) / 256, 256>>>(ei, E);

    gather_kernel<<<(N * 64 + 255) / 256, 256>>>(x, ei, ea, g1, be1, mu1, va1, N, E);

    split_w_kernel<<<(2 * (D * D / 4) + 255) / 256, 256>>>(W1, W2);

    dim3 grid(2, (N + 127) / 128);
    gemm1_tc<<<grid, 512, SM_BYTES>>>(b1, N);
    gemm2_tc<<<grid, 512, SM_BYTES>>>(b2, g2, be2, mu2, va2, out, N);
}